// round 15
// baseline (speedup 1.0000x reference)
#include <cuda_runtime.h>
#include <cuda_bf16.h>
#include <cuda_fp16.h>
#include <math.h>
#include <stdint.h>

#define KB 4
#define KS 2048
#define KE 1024
#define KM 256
#define KF (4 * KE)
#define KT (KB * KS)   // 8192 tokens
#define KC 8           // scan chunks
#define KL (KS / KC)   // 256 steps per chunk
#define KSK 4          // FFN2 split-K factor

// ---------------- scratch (device globals; no runtime allocation) ----------
__device__ __align__(16) float g_k [(size_t)KT * KM];
__device__ __align__(16) float g_q [(size_t)KT * KM];
__device__ __align__(16) float g_v [(size_t)KT * KM];
__device__ float g_beta [KT];
__device__ float g_decay[KT];
__device__ __align__(16) float g_x2[(size_t)KT * KE];
__device__ __align__(16) float g_part[(size_t)KSK * KT * KE];

__device__ __align__(16) float g_delta [(size_t)KC * KB * KM * KM];
__device__ __align__(16) float g_mstart[(size_t)KC * KB * KM * KM];
__device__ float g_dprod[KB * KC];

// fp16 scratch (raw u16)
__device__ __align__(16) uint16_t g_xn_hi[(size_t)KT * KE];
__device__ __align__(16) uint16_t g_xn_lo[(size_t)KT * KE];
__device__ __align__(16) uint16_t g_ro  [(size_t)KT * KM];
__device__ __align__(16) uint16_t g_f1  [(size_t)KT * KF];

__device__ __align__(16) uint16_t g_wkqv_h[(size_t)3 * KM * KE];
__device__ __align__(16) uint16_t g_wo_h[KE * KM];
__device__ __align__(16) uint16_t g_wf1_h[(size_t)KF * KE];
__device__ __align__(16) uint16_t g_wf2_h[(size_t)KE * KF];

// ---------------- small helpers ----------------
__device__ __forceinline__ float warp_sum(float v) {
#pragma unroll
    for (int o = 16; o; o >>= 1) v += __shfl_xor_sync(0xffffffffu, v, o);
    return v;
}
__device__ __forceinline__ float gelu_exact(float v) {
    return 0.5f * v * (1.0f + erff(v * 0.70710678118654752f));
}
__device__ __forceinline__ uint16_t f2h(float x) {
    __half h = __float2half_rn(x);
    return *reinterpret_cast<uint16_t*>(&h);
}
__device__ __forceinline__ float h2f(uint16_t u) {
    __half h = *reinterpret_cast<__half*>(&u);
    return __half2float(h);
}
__device__ __forceinline__ uint32_t s2u(const void* p) {
    uint32_t a;
    asm("{ .reg .u64 t; cvta.to.shared.u64 t, %1; cvt.u32.u64 %0, t; }" : "=r"(a) : "l"(p));
    return a;
}

// ---------------- PTX wrappers ----------------
__device__ __forceinline__ void cp16(uint32_t d, const void* g) {
    asm volatile("cp.async.cg.shared.global [%0], [%1], 16;\n" :: "r"(d), "l"(g));
}
__device__ __forceinline__ void cp_commit() { asm volatile("cp.async.commit_group;\n" ::: "memory"); }
template <int N> __device__ __forceinline__ void cp_wait() {
    asm volatile("cp.async.wait_group %0;\n" :: "n"(N) : "memory");
}
__device__ __forceinline__ void ldsm_x4(uint32_t& r0, uint32_t& r1, uint32_t& r2, uint32_t& r3,
                                        uint32_t addr) {
    asm volatile("ldmatrix.sync.aligned.m8n8.x4.shared.b16 {%0,%1,%2,%3}, [%4];"
                 : "=r"(r0), "=r"(r1), "=r"(r2), "=r"(r3) : "r"(addr));
}
__device__ __forceinline__ void mma_fp16(float& c0, float& c1, float& c2, float& c3,
                                         uint32_t a0, uint32_t a1, uint32_t a2, uint32_t a3,
                                         uint32_t b0, uint32_t b1) {
    asm volatile(
        "mma.sync.aligned.m16n8k16.row.col.f32.f16.f16.f32 "
        "{%0,%1,%2,%3}, {%4,%5,%6,%7}, {%8,%9}, {%0,%1,%2,%3};"
        : "+f"(c0), "+f"(c1), "+f"(c2), "+f"(c3)
        : "r"(a0), "r"(a1), "r"(a2), "r"(a3), "r"(b0), "r"(b1));
}

// ---------------- LayerNorm -> fp16 hi/lo ----------------------------------
__global__ void ln_kernel(const float* __restrict__ x, const float* __restrict__ g,
                          const float* __restrict__ bvec,
                          uint16_t* __restrict__ yhi, uint16_t* __restrict__ ylo) {
    __shared__ float red[2][8];
    const int n = blockIdx.x;
    const int tid = threadIdx.x;
    const float4 xv = ((const float4*)(x + (size_t)n * KE))[tid];
    float s  = xv.x + xv.y + xv.z + xv.w;
    float ss = xv.x * xv.x + xv.y * xv.y + xv.z * xv.z + xv.w * xv.w;
    s = warp_sum(s); ss = warp_sum(ss);
    const int wid = tid >> 5, lane = tid & 31;
    if (lane == 0) { red[0][wid] = s; red[1][wid] = ss; }
    __syncthreads();
    float st = 0.f, sst = 0.f;
#pragma unroll
    for (int w = 0; w < 8; w++) { st += red[0][w]; sst += red[1][w]; }
    const float mu  = st * (1.0f / KE);
    const float var = sst * (1.0f / KE) - mu * mu;
    const float rs  = rsqrtf(var + 1e-5f);
    const float4 gg = ((const float4*)g)[tid];
    const float4 bb = ((const float4*)bvec)[tid];
    float o[4];
    o[0] = (xv.x - mu) * rs * gg.x + bb.x;
    o[1] = (xv.y - mu) * rs * gg.y + bb.y;
    o[2] = (xv.z - mu) * rs * gg.z + bb.z;
    o[3] = (xv.w - mu) * rs * gg.w + bb.w;
    uint16_t h[4], l[4];
#pragma unroll
    for (int e = 0; e < 4; e++) {
        h[e] = f2h(o[e]);
        l[e] = f2h(o[e] - h2f(h[e]));
    }
    const size_t vi = (size_t)n * 256 + tid;
    ((uint2*)yhi)[vi] = make_uint2((uint32_t)h[0] | ((uint32_t)h[1] << 16),
                                   (uint32_t)h[2] | ((uint32_t)h[3] << 16));
    ((uint2*)ylo)[vi] = make_uint2((uint32_t)l[0] | ((uint32_t)l[1] << 16),
                                   (uint32_t)l[2] | ((uint32_t)l[3] << 16));
}

// ---------------- fp32 -> fp16 single convert ------------------------------
__global__ void convh_kernel(const float* __restrict__ src, uint16_t* __restrict__ dst, int n4) {
    const int i0 = (blockIdx.x * 256 + threadIdx.x) * 4;
    if (i0 + 3 < n4) {
        float4 v[4];
#pragma unroll
        for (int j = 0; j < 4; j++) v[j] = ((const float4*)src)[i0 + j];
#pragma unroll
        for (int j = 0; j < 4; j++) {
            ((uint2*)dst)[i0 + j] = make_uint2(
                (uint32_t)f2h(v[j].x) | ((uint32_t)f2h(v[j].y) << 16),
                (uint32_t)f2h(v[j].z) | ((uint32_t)f2h(v[j].w) << 16));
        }
    } else {
        for (int j = 0; j < 4 && i0 + j < n4; j++) {
            const float4 v = ((const float4*)src)[i0 + j];
            ((uint2*)dst)[i0 + j] = make_uint2(
                (uint32_t)f2h(v.x) | ((uint32_t)f2h(v.y) << 16),
                (uint32_t)f2h(v.z) | ((uint32_t)f2h(v.w) << 16));
        }
    }
}

__global__ void convh3_kernel(const float* __restrict__ s0, const float* __restrict__ s1,
                              const float* __restrict__ s2,
                              uint16_t* __restrict__ dst, int n4each) {
    const int i = blockIdx.x * 256 + threadIdx.x;
    if (i >= 3 * n4each) return;
    const float* src;
    int j;
    if (i < n4each) { src = s0; j = i; }
    else if (i < 2 * n4each) { src = s1; j = i - n4each; }
    else { src = s2; j = i - 2 * n4each; }
    const float4 v = ((const float4*)src)[j];
    ((uint2*)dst)[i] = make_uint2((uint32_t)f2h(v.x) | ((uint32_t)f2h(v.y) << 16),
                                  (uint32_t)f2h(v.z) | ((uint32_t)f2h(v.w) << 16));
}

// ---------------- postproc -------------------------------------------------
__global__ void postproc_kernel(const float* __restrict__ wgw, const float* __restrict__ bgw,
                                const float* __restrict__ wgf, const float* __restrict__ bgf) {
    __shared__ float red[4][8];
    const int n = blockIdx.x;
    const int i = threadIdx.x;
    const size_t off = (size_t)n * KM + i;
    const float kv = g_k[off];
    const float qv = g_q[off];
    const size_t vi = (size_t)n * 256 + i;
    const uint2 hx = ((const uint2*)g_xn_hi)[vi];
    const uint2 lx = ((const uint2*)g_xn_lo)[vi];
    float xr[4];
    xr[0] = h2f((uint16_t)hx.x) + h2f((uint16_t)lx.x);
    xr[1] = h2f((uint16_t)(hx.x >> 16)) + h2f((uint16_t)(lx.x >> 16));
    xr[2] = h2f((uint16_t)hx.y) + h2f((uint16_t)lx.y);
    xr[3] = h2f((uint16_t)(hx.y >> 16)) + h2f((uint16_t)(lx.y >> 16));
    const float4 wg = ((const float4*)wgw)[i];
    const float4 wf = ((const float4*)wgf)[i];
    float dg = xr[0] * wg.x + xr[1] * wg.y + xr[2] * wg.z + xr[3] * wg.w;
    float df = xr[0] * wf.x + xr[1] * wf.y + xr[2] * wf.z + xr[3] * wf.w;
    float sk = warp_sum(kv * kv);
    float sq = warp_sum(qv * qv);
    dg = warp_sum(dg);
    df = warp_sum(df);
    const int wid = i >> 5, lane = i & 31;
    if (lane == 0) { red[0][wid] = sk; red[1][wid] = sq; red[2][wid] = dg; red[3][wid] = df; }
    __syncthreads();
    float tk = 0.f, tq = 0.f, tg = 0.f, tf = 0.f;
#pragma unroll
    for (int w = 0; w < 8; w++) { tk += red[0][w]; tq += red[1][w]; tg += red[2][w]; tf += red[3][w]; }
    const float kn = fmaxf(sqrtf(tk), 1e-12f);
    const float qn = fmaxf(sqrtf(tq), 1e-12f);
    g_k[off] = kv / kn;
    g_q[off] = qv / qn;
    if (i == 0) {
        g_beta[n]  = 1.0f / (1.0f + expf(-(tg + bgw[0])));
        g_decay[n] = 1.0f / (1.0f + expf(-(tf + bgf[0])));
    }
}

// ---------------- chunked scan --------------------------------------------
__global__ void chunkprod_kernel() {
    __shared__ float red[8];
    const int b = blockIdx.x >> 3;
    const int c = blockIdx.x & 7;
    const int tid = threadIdx.x;
    float d = g_decay[(size_t)b * KS + c * KL + tid];
#pragma unroll
    for (int o = 16; o; o >>= 1) d *= __shfl_xor_sync(0xffffffffu, d, o);
    if ((tid & 31) == 0) red[tid >> 5] = d;
    __syncthreads();
    if (tid == 0) {
        float p = 1.f;
#pragma unroll
        for (int w = 0; w < 8; w++) p *= red[w];
        g_dprod[b * KC + c] = p;
    }
}

__global__ void scanA_kernel() {
    const int blk = blockIdx.x;
    const int c = blk >> 7;
    const int rem = blk & 127;
    const int b = rem >> 5;
    const int i = ((rem & 31) << 3) + (threadIdx.x >> 5);
    const int lane = threadIdx.x & 31;
    const int t0 = c * KL;

    const float* kb = g_k + ((size_t)b * KS + t0) * KM + lane * 8;
    const float* vb = g_v + ((size_t)b * KS + t0) * KM + i;
    const float* bb = g_beta  + (size_t)b * KS + t0;
    const float* db = g_decay + (size_t)b * KS + t0;

    float m[8] = {0.f, 0.f, 0.f, 0.f, 0.f, 0.f, 0.f, 0.f};

    float4 k0a = *(const float4*)(kb),      k0c = *(const float4*)(kb + 4);
    float4 k1a = *(const float4*)(kb + KM), k1c = *(const float4*)(kb + KM + 4);

    for (int tt = 0; tt < KL; tt += 2) {
        const float4 ck0a = k0a, ck0c = k0c, ck1a = k1a, ck1c = k1c;
        const float vv0 = vb[(size_t)tt * KM];
        const float vv1 = vb[(size_t)(tt + 1) * KM];
        const float bt0 = bb[tt], bt1 = bb[tt + 1];
        const float dt0 = db[tt], dt1 = db[tt + 1];
        if (tt + 2 < KL) {
            const float* kn = kb + (size_t)(tt + 2) * KM;
            k0a = *(const float4*)(kn);       k0c = *(const float4*)(kn + 4);
            k1a = *(const float4*)(kn + KM);  k1c = *(const float4*)(kn + KM + 4);
        }
        const float c0 = bt0 * vv0;
        m[0] = dt0*m[0] + c0*ck0a.x;  m[1] = dt0*m[1] + c0*ck0a.y;
        m[2] = dt0*m[2] + c0*ck0a.z;  m[3] = dt0*m[3] + c0*ck0a.w;
        m[4] = dt0*m[4] + c0*ck0c.x;  m[5] = dt0*m[5] + c0*ck0c.y;
        m[6] = dt0*m[6] + c0*ck0c.z;  m[7] = dt0*m[7] + c0*ck0c.w;
        const float c1 = bt1 * vv1;
        m[0] = dt1*m[0] + c1*ck1a.x;  m[1] = dt1*m[1] + c1*ck1a.y;
        m[2] = dt1*m[2] + c1*ck1a.z;  m[3] = dt1*m[3] + c1*ck1a.w;
        m[4] = dt1*m[4] + c1*ck1c.x;  m[5] = dt1*m[5] + c1*ck1c.y;
        m[6] = dt1*m[6] + c1*ck1c.z;  m[7] = dt1*m[7] + c1*ck1c.w;
    }
    const size_t dbase = ((((size_t)c * KB + b) * KM + i) * KM) + lane * 8;
    *(float4*)(g_delta + dbase)     = make_float4(m[0], m[1], m[2], m[3]);
    *(float4*)(g_delta + dbase + 4) = make_float4(m[4], m[5], m[6], m[7]);
}

__global__ void scanB_kernel(const float* __restrict__ mem0, float* __restrict__ mem_out) {
    const int b = blockIdx.x >> 8;
    const int i = blockIdx.x & 255;
    const int j = threadIdx.x;
    const size_t base = ((size_t)b * KM + i) * KM + j;
    float m = mem0[base];
#pragma unroll
    for (int c = 0; c < KC; c++) {
        const size_t idx = ((((size_t)c * KB + b) * KM + i) * KM) + j;
        g_mstart[idx] = m;
        m = g_dprod[b * KC + c] * m + g_delta[idx];
    }
    mem_out[base] = m;
}

__global__ void scanC_kernel() {
    const int blk = blockIdx.x;
    const int c = blk >> 7;
    const int rem = blk & 127;
    const int b = rem >> 5;
    const int i = ((rem & 31) << 3) + (threadIdx.x >> 5);
    const int lane = threadIdx.x & 31;
    const int t0 = c * KL;

    const size_t sbase = ((((size_t)c * KB + b) * KM + i) * KM) + lane * 8;
    float m[8];
    { float4 a = *(const float4*)(g_mstart + sbase);
      float4 cc = *(const float4*)(g_mstart + sbase + 4);
      m[0]=a.x; m[1]=a.y; m[2]=a.z; m[3]=a.w; m[4]=cc.x; m[5]=cc.y; m[6]=cc.z; m[7]=cc.w; }

    const float* kb = g_k + ((size_t)b * KS + t0) * KM + lane * 8;
    const float* qb = g_q + ((size_t)b * KS + t0) * KM + lane * 8;
    const float* vb = g_v + ((size_t)b * KS + t0) * KM + i;
    const float* bb = g_beta  + (size_t)b * KS + t0;
    const float* db = g_decay + (size_t)b * KS + t0;
    uint16_t* ro = g_ro + ((size_t)b * KS + t0) * KM + i;

    float4 q0a = *(const float4*)(qb),            q0c = *(const float4*)(qb + 4);
    float4 k0a = *(const float4*)(kb),            k0c = *(const float4*)(kb + 4);
    float4 q1a = *(const float4*)(qb + KM),       q1c = *(const float4*)(qb + KM + 4);
    float4 k1a = *(const float4*)(kb + KM),       k1c = *(const float4*)(kb + KM + 4);

    float pp0 = 0.f, pp1 = 0.f;

    for (int tt = 0; tt < KL; tt += 2) {
        const float4 cq0a = q0a, cq0c = q0c, ck0a = k0a, ck0c = k0c;
        const float4 cq1a = q1a, cq1c = q1c, ck1a = k1a, ck1c = k1c;
        const float vv0 = vb[(size_t)tt * KM];
        const float vv1 = vb[(size_t)(tt + 1) * KM];
        const float bt0 = bb[tt], bt1 = bb[tt + 1];
        const float dt0 = db[tt], dt1 = db[tt + 1];
        if (tt + 2 < KL) {
            const float* qn = qb + (size_t)(tt + 2) * KM;
            const float* kn = kb + (size_t)(tt + 2) * KM;
            q0a = *(const float4*)(qn);       q0c = *(const float4*)(qn + 4);
            k0a = *(const float4*)(kn);       k0c = *(const float4*)(kn + 4);
            q1a = *(const float4*)(qn + KM);  q1c = *(const float4*)(qn + KM + 4);
            k1a = *(const float4*)(kn + KM);  k1c = *(const float4*)(kn + KM + 4);
        }
        float pl0 = m[0]*cq0a.x + m[1]*cq0a.y + m[2]*cq0a.z + m[3]*cq0a.w
                  + m[4]*cq0c.x + m[5]*cq0c.y + m[6]*cq0c.z + m[7]*cq0c.w;
        const float c0 = bt0 * vv0;
        m[0] = dt0*m[0] + c0*ck0a.x;  m[1] = dt0*m[1] + c0*ck0a.y;
        m[2] = dt0*m[2] + c0*ck0a.z;  m[3] = dt0*m[3] + c0*ck0a.w;
        m[4] = dt0*m[4] + c0*ck0c.x;  m[5] = dt0*m[5] + c0*ck0c.y;
        m[6] = dt0*m[6] + c0*ck0c.z;  m[7] = dt0*m[7] + c0*ck0c.w;
        float pl1 = m[0]*cq1a.x + m[1]*cq1a.y + m[2]*cq1a.z + m[3]*cq1a.w
                  + m[4]*cq1c.x + m[5]*cq1c.y + m[6]*cq1c.z + m[7]*cq1c.w;
        const float c1 = bt1 * vv1;
#pragma unroll
        for (int o = 16; o; o >>= 1) {
            pp0 += __shfl_xor_sync(0xffffffffu, pp0, o);
            pp1 += __shfl_xor_sync(0xffffffffu, pp1, o);
        }
        m[0] = dt1*m[0] + c1*ck1a.x;  m[1] = dt1*m[1] + c1*ck1a.y;
        m[2] = dt1*m[2] + c1*ck1a.z;  m[3] = dt1*m[3] + c1*ck1a.w;
        m[4] = dt1*m[4] + c1*ck1c.x;  m[5] = dt1*m[5] + c1*ck1c.y;
        m[6] = dt1*m[6] + c1*ck1c.z;  m[7] = dt1*m[7] + c1*ck1c.w;
        if (lane == 0 && tt > 0) {
            ro[(size_t)(tt - 2) * KM] = f2h(pp0);
            ro[(size_t)(tt - 1) * KM] = f2h(pp1);
        }
        pp0 = pl0;
        pp1 = pl1;
    }
#pragma unroll
    for (int o = 16; o; o >>= 1) {
        pp0 += __shfl_xor_sync(0xffffffffu, pp0, o);
        pp1 += __shfl_xor_sync(0xffffffffu, pp1, o);
    }
    if (lane == 0) {
        ro[(size_t)(KL - 2) * KM] = f2h(pp0);
        ro[(size_t)(KL - 1) * KM] = f2h(pp1);
    }
}

// ---------------- GEMM geometry ---------------------------------------------
#define ROWE 40
#define TSZ  (128 * ROWE * 2)

// ---------------- fp16x2 fused-term GEMM (kqv, BK=32, unchanged) -----------
#define F2STAGE (3 * TSZ)
#define F2SMEM  (2 * F2STAGE)   // 61440

__global__ void __launch_bounds__(128, 3)
gemm_kqv(const uint16_t* __restrict__ Ahi, const uint16_t* __restrict__ Alo,
         const uint16_t* __restrict__ B,
         float* __restrict__ Ok, float* __restrict__ Oq, float* __restrict__ Ov,
         const float* __restrict__ bk, const float* __restrict__ bq, const float* __restrict__ bv,
         int K) {
    extern __shared__ __align__(16) uint8_t smem[];
    const uint32_t sm0 = s2u(smem);

    const int tid = threadIdx.x;
    const int wid = tid >> 5;
    const int lane = tid & 31;
    const int warp_m = wid >> 1;
    const int warp_n = wid & 1;

    const int row0 = blockIdx.y * 128;
    const int col0 = blockIdx.x * 128;
    const int kcs = K >> 5;

    auto load_stage = [&](int chunk, int buf) {
        const int k0 = chunk << 5;
        const uint32_t s0 = sm0 + buf * F2STAGE;
#pragma unroll
        for (int i = 0; i < 4; i++) {
            const int idx = tid + i * 128;
            const int row = idx >> 2, c = idx & 3;
            const uint32_t so = (uint32_t)(row * ROWE) * 2 + c * 16;
            cp16(s0 + so,           Ahi + (size_t)(row0 + row) * K + k0 + c * 8);
            cp16(s0 + TSZ + so,     Alo + (size_t)(row0 + row) * K + k0 + c * 8);
            cp16(s0 + 2 * TSZ + so, B   + (size_t)(col0 + row) * K + k0 + c * 8);
        }
    };

    float acc[4][8][4];
#pragma unroll
    for (int mt = 0; mt < 4; mt++)
#pragma unroll
        for (int nt = 0; nt < 8; nt++)
#pragma unroll
            for (int e = 0; e < 4; e++) acc[mt][nt][e] = 0.f;

    const int a_row = warp_m * 64 + (lane & 15);
    const int a_col8 = (lane >> 4) * 8;
    const int b_local = lane & 7;
    const int b_sel = lane >> 3;
    const int b_nrow = warp_n * 64 + ((b_sel >> 1) & 1) * 8 + b_local;
    const int b_k8 = (b_sel & 1) * 8;

    load_stage(0, 0);
    cp_commit();

    for (int it = 0; it < kcs; it++) {
        const int buf = it & 1;
        cp_wait<0>();
        __syncthreads();
        if (it + 1 < kcs) { load_stage(it + 1, 1 - buf); cp_commit(); }

        const uint32_t sah = sm0 + buf * F2STAGE;
        const uint32_t sal = sah + TSZ;
        const uint32_t sb  = sah + 2 * TSZ;
#pragma unroll
        for (int j = 0; j < 2; j++) {
            uint32_t b[8][2];
#pragma unroll
            for (int nt2 = 0; nt2 < 4; nt2++) {
                const uint32_t addr = sb + (uint32_t)((b_nrow + nt2 * 16) * ROWE + j * 16 + b_k8) * 2;
                uint32_t r0, r1, r2, r3;
                ldsm_x4(r0, r1, r2, r3, addr);
                b[nt2 * 2][0] = r0; b[nt2 * 2][1] = r1;
                b[nt2 * 2 + 1][0] = r2; b[nt2 * 2 + 1][1] = r3;
            }
            uint32_t a[4][4];
#pragma unroll
            for (int mt = 0; mt < 4; mt++) {
                const uint32_t addr = sah + (uint32_t)((a_row + mt * 16) * ROWE + j * 16 + a_col8) * 2;
                ldsm_x4(a[mt][0], a[mt][1], a[mt][2], a[mt][3], addr);
            }
#pragma unroll
            for (int mt = 0; mt < 4; mt++)
#pragma unroll
                for (int nt = 0; nt < 8; nt++)
                    mma_fp16(acc[mt][nt][0], acc[mt][nt][1], acc[mt][nt][2], acc[mt][nt][3],
                             a[mt][0], a[mt][1], a[mt][2], a[mt][3], b[nt][0], b[nt][1]);
#pragma unroll
            for (int mt = 0; mt < 4; mt++) {
                const uint32_t addr = sal + (uint32_t)((a_row + mt * 16) * ROWE + j * 16 + a_col8) * 2;
                ldsm_x4(a[mt][0], a[mt][1], a[mt][2], a[mt][3], addr);
            }
#pragma unroll
            for (int mt = 0; mt < 4; mt++)
#pragma unroll
                for (int nt = 0; nt < 8; nt++)
                    mma_fp16(acc[mt][nt][0], acc[mt][nt][1], acc[mt][nt][2], acc[mt][nt][3],
                             a[mt][0], a[mt][1], a[mt][2], a[mt][3], b[nt][0], b[nt][1]);
        }
    }

    const int er = lane >> 2;
    const int ec = (lane & 3) * 2;

    const int seg = blockIdx.x >> 1;
    const int segoff = (blockIdx.x & 1) * 128;
    const float* bseg = (seg == 1) ? bq : (seg == 2) ? bv : bk;
    float* oseg = (seg == 1) ? Oq : (seg == 2) ? Ov : Ok;
    const bool do_tanh = (seg == 2);

#pragma unroll
    for (int nt = 0; nt < 8; nt++) {
        const int clt = warp_n * 64 + nt * 8 + ec;
        const int cl = segoff + clt;
        const float b0 = __ldg(bseg + cl);
        const float b1 = __ldg(bseg + cl + 1);
#pragma unroll
        for (int mt = 0; mt < 4; mt++) {
            const int rl = row0 + warp_m * 64 + mt * 16 + er;
#pragma unroll
            for (int half = 0; half < 2; half++) {
                const size_t r = (size_t)(rl + half * 8);
                float v0 = acc[mt][nt][half * 2 + 0] + b0;
                float v1 = acc[mt][nt][half * 2 + 1] + b1;
                if (do_tanh) { v0 = tanhf(v0); v1 = tanhf(v1); }
                *(float2*)(oseg + r * KM + cl) = make_float2(v0, v1);
            }
        }
    }
}

// ---------------- fp16x1 single-term GEMM, BK=64, 2-stage --------------------
// EPI: 2 = bias+residual->fp32; 3 = bias+gelu->fp16; 4 = raw partial (split-K)
#define ROWE2 72
#define T64   (128 * ROWE2 * 2)     // 18432
#define G1STAGE (2 * T64)           // 36864
#define G1SMEM  (2 * G1STAGE)       // 73728

template <int EPI>
__global__ void __launch_bounds__(128, 3)
gemm1t(const uint16_t* __restrict__ A, const uint16_t* __restrict__ B,
       const float* __restrict__ bias, const float* __restrict__ res,
       float* __restrict__ Cf, uint16_t* __restrict__ C16, float* __restrict__ Part,
       int Kstride, int klen, int N) {
    extern __shared__ __align__(16) uint8_t smem[];
    const uint32_t sm0 = s2u(smem);

    const int tid = threadIdx.x;
    const int wid = tid >> 5;
    const int lane = tid & 31;
    const int warp_m = wid >> 1;
    const int warp_n = wid & 1;

    const int row0 = blockIdx.y * 128;
    const int col0 = blockIdx.x * 128;
    const int koff = blockIdx.z * klen;
    const int kcs = klen >> 6;

    auto load_stage = [&](int chunk, int buf) {
        const int k0 = koff + (chunk << 6);
        const uint32_t sa = sm0 + buf * G1STAGE;
        const uint32_t sb = sa + T64;
#pragma unroll
        for (int i = 0; i < 8; i++) {
            const int idx = tid + i * 128;        // 0..1023
            const int row = idx >> 3, c = idx & 7;
            cp16(sa + (uint32_t)(row * ROWE2) * 2 + c * 16,
                 A + (size_t)(row0 + row) * Kstride + k0 + c * 8);
            cp16(sb + (uint32_t)(row * ROWE2) * 2 + c * 16,
                 B + (size_t)(col0 + row) * Kstride + k0 + c * 8);
        }
    };

    float acc[4][8][4];
#pragma unroll
    for (int mt = 0; mt < 4; mt++)
#pragma unroll
        for (int nt = 0; nt < 8; nt++)
#pragma unroll
            for (int e = 0; e < 4; e++) acc[mt][nt][e] = 0.f;

    const int a_row = warp_m * 64 + (lane & 15);
    const int a_col8 = (lane >> 4) * 8;
    const int b_local = lane & 7;
    const int b_sel = lane >> 3;
    const int b_nrow = warp_n * 64 + ((b_sel >> 1) & 1) * 8 + b_local;
    const int b_k8 = (b_sel & 1) * 8;

    load_stage(0, 0);
    cp_commit();

    for (int it = 0; it < kcs; it++) {
        const int buf = it & 1;
        cp_wait<0>();
        __syncthreads();
        if (it + 1 < kcs) { load_stage(it + 1, 1 - buf); cp_commit(); }

        const uint32_t sa = sm0 + buf * G1STAGE;
        const uint32_t sb = sa + T64;
#pragma unroll
        for (int j = 0; j < 4; j++) {
            uint32_t a[4][4];
#pragma unroll
            for (int mt = 0; mt < 4; mt++) {
                const uint32_t addr = sa + (uint32_t)((a_row + mt * 16) * ROWE2 + j * 16 + a_col8) * 2;
                ldsm_x4(a[mt][0], a[mt][1], a[mt][2], a[mt][3], addr);
            }
            uint32_t b[8][2];
#pragma unroll
            for (int nt2 = 0; nt2 < 4; nt2++) {
                const uint32_t addr = sb + (uint32_t)((b_nrow + nt2 * 16) * ROWE2 + j * 16 + b_k8) * 2;
                uint32_t r0, r1, r2, r3;
                ldsm_x4(r0, r1, r2, r3, addr);
                b[nt2 * 2][0] = r0; b[nt2 * 2][1] = r1;
                b[nt2 * 2 + 1][0] = r2; b[nt2 * 2 + 1][1] = r3;
            }
#pragma unroll
            for (int mt = 0; mt < 4; mt++)
#pragma unroll
                for (int nt = 0; nt < 8; nt++)
                    mma_fp16(acc[mt][nt][0], acc[mt][nt][1], acc[mt][nt][2], acc[mt][nt][3],
                             a[mt][0], a[mt][1], a[mt][2], a[mt][3], b[nt][0], b[nt][1]);
        }
    }

    const int er = lane >> 2;
    const int ec = (lane & 3) * 2;
    float* part = (EPI == 4) ? Part + (size_t)blockIdx.z * KT * KE : nullptr;

#pragma unroll
    for (int nt = 0; nt < 8; nt++) {
        const int c = col0 + warp_n * 64 + nt * 8 + ec;
        const float b0 = (EPI == 4) ? 0.f : __ldg(bias + c);
        const float b1 = (EPI == 4) ? 0.f : __ldg(bias + c + 1);
#pragma unroll
        for (int mt = 0; mt < 4; mt++) {
            const int rl = row0 + warp_m * 64 + mt * 16 + er;
#pragma unroll
            for (int half = 0; half < 2; half++) {
                const size_t r = (size_t)(rl + half * 8);
                float v0 = acc[mt][nt][half * 2 + 0] + b0;
                float v1 = acc[mt][nt][half * 2 + 1] + b1;
                if (EPI == 2) {
                    const float2 rv = *(const float2*)(res + r * N + c);
                    v0 += rv.x; v1 += rv.y;
                    *(float2*)(Cf + r * N + c) = make_float2(v0, v1);
                } else if (EPI == 3) {
                    v0 = gelu_exact(v0); v1 = gelu_exact(v1);
                    *(uint32_t*)(C16 + r * N + c) = (uint32_t)f2h(v0) | ((uint32_t)f2h(v1) << 16);
                } else {
                    *(float2*)(part + r * N + c) = make_float2(v0, v1);
                }
            }
        }
    }
}

// ---------------- split-K reduce: out = x2 + bias + sum(partials) -----------
__global__ void reduce_kernel(const float* __restrict__ x2, const float* __restrict__ bias,
                              float* __restrict__ out) {
    const size_t i = (size_t)blockIdx.x * 256 + threadIdx.x;   // float4 index
    const int c4 = (int)(i & (KE / 4 - 1));
    const float4 bv = ((const float4*)bias)[c4];
    float4 s = ((const float4*)g_part)[i];
    const float4 p1 = ((const float4*)(g_part + (size_t)KT * KE))[i];
    const float4 p2 = ((const float4*)(g_part + (size_t)2 * KT * KE))[i];
    const float4 p3 = ((const float4*)(g_part + (size_t)3 * KT * KE))[i];
    const float4 xv = ((const float4*)x2)[i];
    s.x = s.x + p1.x + p2.x + p3.x + xv.x + bv.x;
    s.y = s.y + p1.y + p2.y + p3.y + xv.y + bv.y;
    s.z = s.z + p1.z + p2.z + p3.z + xv.z + bv.z;
    s.w = s.w + p1.w + p2.w + p3.w + xv.w + bv.w;
    ((float4*)out)[i] = s;
}

// ---------------- launch ----------------
extern "C" void kernel_launch(void* const* d_in, const int* in_sizes, int n_in,
                              void* d_out, int out_size) {
    (void)in_sizes; (void)n_in; (void)out_size;
    const float* x      = (const float*)d_in[0];
    const float* memory = (const float*)d_in[1];
    const float* w_k    = (const float*)d_in[2];
    const float* b_k    = (const float*)d_in[3];
    const float* w_q    = (const float*)d_in[4];
    const float* b_q    = (const float*)d_in[5];
    const float* w_v    = (const float*)d_in[6];
    const float* b_v    = (const float*)d_in[7];
    const float* w_out  = (const float*)d_in[8];
    const float* b_out  = (const float*)d_in[9];
    const float* w_gw   = (const float*)d_in[10];
    const float* b_gw   = (const float*)d_in[11];
    const float* w_gf   = (const float*)d_in[12];
    const float* b_gf   = (const float*)d_in[13];
    const float* ln1_g  = (const float*)d_in[14];
    const float* ln1_b  = (const float*)d_in[15];
    const float* ln2_g  = (const float*)d_in[16];
    const float* ln2_b  = (const float*)d_in[17];
    const float* w_f1   = (const float*)d_in[18];
    const float* b_f1   = (const float*)d_in[19];
    const float* w_f2   = (const float*)d_in[20];
    const float* b_f2   = (const float*)d_in[21];

    float* out_x   = (float*)d_out;
    float* out_mem = out_x + (size_t)KT * KE;

    float *p_k, *p_q, *p_v, *p_x2;
    uint16_t *p_xnh, *p_xnl, *p_ro, *p_f1;
    uint16_t *p_wkqv, *p_wo, *p_wf1, *p_wf2;
    cudaGetSymbolAddress((void**)&p_k,    g_k);
    cudaGetSymbolAddress((void**)&p_q,    g_q);
    cudaGetSymbolAddress((void**)&p_v,    g_v);
    cudaGetSymbolAddress((void**)&p_x2,   g_x2);
    cudaGetSymbolAddress((void**)&p_xnh,  g_xn_hi);
    cudaGetSymbolAddress((void**)&p_xnl,  g_xn_lo);
    cudaGetSymbolAddress((void**)&p_ro,   g_ro);
    cudaGetSymbolAddress((void**)&p_f1,   g_f1);
    cudaGetSymbolAddress((void**)&p_wkqv, g_wkqv_h);
    cudaGetSymbolAddress((void**)&p_wo,   g_wo_h);
    cudaGetSymbolAddress((void**)&p_wf1,  g_wf1_h);
    cudaGetSymbolAddress((void**)&p_wf2,  g_wf2_h);

    cudaFuncSetAttribute(gemm_kqv,  cudaFuncAttributeMaxDynamicSharedMemorySize, F2SMEM);
    cudaFuncSetAttribute(gemm1t<2>, cudaFuncAttributeMaxDynamicSharedMemorySize, G1SMEM);
    cudaFuncSetAttribute(gemm1t<3>, cudaFuncAttributeMaxDynamicSharedMemorySize, G1SMEM);
    cudaFuncSetAttribute(gemm1t<4>, cudaFuncAttributeMaxDynamicSharedMemorySize, G1SMEM);

    // launch order: ncu captures OUR index 3 -> kqv GEMM (probe)
    // 0) fused convert of w_k|w_q|w_v -> fp16
    convh3_kernel<<<768, 256>>>(w_k, w_q, w_v, p_wkqv, KM*KE/4);
    // 1) LN1 -> xn fp16 hi/lo
    ln_kernel<<<KT, 256>>>(x, ln1_g, ln1_b, p_xnh, p_xnl);
    // 2) convert w_out -> fp16
    convh_kernel<<<(KE*KM/4 + 1023)/1024, 256>>>(w_out, p_wo, KE*KM/4);
    // 3) fused kqv GEMM (fp16x2 fused-term)  [profiled]
    gemm_kqv<<<dim3(6, KT/128), 128, F2SMEM>>>(
        p_xnh, p_xnl, p_wkqv, p_k, p_q, p_v, b_k, b_q, b_v, KE);
    // 4-5) convert FFN weights -> fp16
    convh_kernel<<<(KF*KE/4 + 1023)/1024, 256>>>(w_f1, p_wf1, KF*KE/4);
    convh_kernel<<<(KE*KF/4 + 1023)/1024, 256>>>(w_f2, p_wf2, KE*KF/4);
    // 6) l2norm + gates
    postproc_kernel<<<KT, 256>>>(w_gw, b_gw, w_gf, b_gf);
    // 7) chunk decay products
    chunkprod_kernel<<<KB * KC, KL>>>();
    // 8) scan pass A
    scanA_kernel<<<KC * KB * 32, 256>>>();
    // 9) scan pass B (+ final memory output)
    scanB_kernel<<<KB * KM, 256>>>(memory, out_mem);
    // 10) scan pass C (readouts -> fp16 single)
    scanC_kernel<<<KC * KB * 32, 256>>>();
    // 11) out projection + residual(x) -> x2 (fp16x1, BK=64)
    gemm1t<2><<<dim3(KE/128, KT/128), 128, G1SMEM>>>(
        p_ro, p_wo, b_out, x, p_x2, nullptr, nullptr, KM, KM, KE);
    // 12) LN2 -> xn fp16 hi/lo (FFN1 reads hi only)
    ln_kernel<<<KT, 256>>>(p_x2, ln2_g, ln2_b, p_xnh, p_xnl);
    // 13) FFN1 + GELU -> f1 fp16 single (fp16x1, BK=64)
    gemm1t<3><<<dim3(KF/128, KT/128), 128, G1SMEM>>>(
        p_xnh, p_wf1, b_f1, nullptr, nullptr, p_f1, nullptr, KE, KE, KF);
    // 14) FFN2 split-K=4 -> partials (fp16x1, BK=64)
    {
        float* p_part;
        cudaGetSymbolAddress((void**)&p_part, g_part);
        gemm1t<4><<<dim3(KE/128, KT/128, KSK), 128, G1SMEM>>>(
            p_f1, p_wf2, nullptr, nullptr, nullptr, nullptr, p_part, KF, KF/KSK, KE);
    }
    // 15) reduce partials + bias + residual(x2) -> out
    reduce_kernel<<<KT * KE / 4 / 256, 256>>>(p_x2, b_f2, out_x);
}

// round 16
// speedup vs baseline: 1.5299x; 1.5299x over previous
#include <cuda_runtime.h>
#include <cuda_bf16.h>
#include <cuda_fp16.h>
#include <math.h>
#include <stdint.h>

#define KB 4
#define KS 2048
#define KE 1024
#define KM 256
#define KF (4 * KE)
#define KT (KB * KS)   // 8192 tokens
#define KC 8           // scan chunks
#define KL (KS / KC)   // 256 steps per chunk
#define KSK 2          // FFN2 split-K factor

// ---------------- scratch (device globals; no runtime allocation) ----------
__device__ __align__(16) float g_k [(size_t)KT * KM];
__device__ __align__(16) float g_q [(size_t)KT * KM];
__device__ __align__(16) float g_v [(size_t)KT * KM];
__device__ float g_beta [KT];
__device__ float g_decay[KT];
__device__ __align__(16) float g_x2[(size_t)KT * KE];
__device__ __align__(16) float g_part[(size_t)KSK * KT * KE];

__device__ __align__(16) float g_delta [(size_t)KC * KB * KM * KM];
__device__ __align__(16) float g_mstart[(size_t)KC * KB * KM * KM];
__device__ float g_dprod[KB * KC];

// fp16 scratch (raw u16)
__device__ __align__(16) uint16_t g_xn_hi[(size_t)KT * KE];
__device__ __align__(16) uint16_t g_xn_lo[(size_t)KT * KE];
__device__ __align__(16) uint16_t g_ro  [(size_t)KT * KM];
__device__ __align__(16) uint16_t g_f1  [(size_t)KT * KF];

__device__ __align__(16) uint16_t g_wkqv_h[(size_t)3 * KM * KE];
__device__ __align__(16) uint16_t g_wo_h[KE * KM];
__device__ __align__(16) uint16_t g_wf1_h[(size_t)KF * KE];
__device__ __align__(16) uint16_t g_wf2_h[(size_t)KE * KF];

// ---------------- small helpers ----------------
__device__ __forceinline__ float warp_sum(float v) {
#pragma unroll
    for (int o = 16; o; o >>= 1) v += __shfl_xor_sync(0xffffffffu, v, o);
    return v;
}
__device__ __forceinline__ float gelu_exact(float v) {
    return 0.5f * v * (1.0f + erff(v * 0.70710678118654752f));
}
__device__ __forceinline__ uint16_t f2h(float x) {
    __half h = __float2half_rn(x);
    return *reinterpret_cast<uint16_t*>(&h);
}
__device__ __forceinline__ float h2f(uint16_t u) {
    __half h = *reinterpret_cast<__half*>(&u);
    return __half2float(h);
}
__device__ __forceinline__ uint32_t s2u(const void* p) {
    uint32_t a;
    asm("{ .reg .u64 t; cvta.to.shared.u64 t, %1; cvt.u32.u64 %0, t; }" : "=r"(a) : "l"(p));
    return a;
}

// ---------------- PTX wrappers ----------------
__device__ __forceinline__ void cp16(uint32_t d, const void* g) {
    asm volatile("cp.async.cg.shared.global [%0], [%1], 16;\n" :: "r"(d), "l"(g));
}
__device__ __forceinline__ void cp_commit() { asm volatile("cp.async.commit_group;\n" ::: "memory"); }
template <int N> __device__ __forceinline__ void cp_wait() {
    asm volatile("cp.async.wait_group %0;\n" :: "n"(N) : "memory");
}
__device__ __forceinline__ void ldsm_x4(uint32_t& r0, uint32_t& r1, uint32_t& r2, uint32_t& r3,
                                        uint32_t addr) {
    asm volatile("ldmatrix.sync.aligned.m8n8.x4.shared.b16 {%0,%1,%2,%3}, [%4];"
                 : "=r"(r0), "=r"(r1), "=r"(r2), "=r"(r3) : "r"(addr));
}
__device__ __forceinline__ void mma_fp16(float& c0, float& c1, float& c2, float& c3,
                                         uint32_t a0, uint32_t a1, uint32_t a2, uint32_t a3,
                                         uint32_t b0, uint32_t b1) {
    asm volatile(
        "mma.sync.aligned.m16n8k16.row.col.f32.f16.f16.f32 "
        "{%0,%1,%2,%3}, {%4,%5,%6,%7}, {%8,%9}, {%0,%1,%2,%3};"
        : "+f"(c0), "+f"(c1), "+f"(c2), "+f"(c3)
        : "r"(a0), "r"(a1), "r"(a2), "r"(a3), "r"(b0), "r"(b1));
}

// ---------------- LayerNorm -> fp16 hi/lo ----------------------------------
__global__ void ln_kernel(const float* __restrict__ x, const float* __restrict__ g,
                          const float* __restrict__ bvec,
                          uint16_t* __restrict__ yhi, uint16_t* __restrict__ ylo) {
    __shared__ float red[2][8];
    const int n = blockIdx.x;
    const int tid = threadIdx.x;
    const float4 xv = ((const float4*)(x + (size_t)n * KE))[tid];
    float s  = xv.x + xv.y + xv.z + xv.w;
    float ss = xv.x * xv.x + xv.y * xv.y + xv.z * xv.z + xv.w * xv.w;
    s = warp_sum(s); ss = warp_sum(ss);
    const int wid = tid >> 5, lane = tid & 31;
    if (lane == 0) { red[0][wid] = s; red[1][wid] = ss; }
    __syncthreads();
    float st = 0.f, sst = 0.f;
#pragma unroll
    for (int w = 0; w < 8; w++) { st += red[0][w]; sst += red[1][w]; }
    const float mu  = st * (1.0f / KE);
    const float var = sst * (1.0f / KE) - mu * mu;
    const float rs  = rsqrtf(var + 1e-5f);
    const float4 gg = ((const float4*)g)[tid];
    const float4 bb = ((const float4*)bvec)[tid];
    float o[4];
    o[0] = (xv.x - mu) * rs * gg.x + bb.x;
    o[1] = (xv.y - mu) * rs * gg.y + bb.y;
    o[2] = (xv.z - mu) * rs * gg.z + bb.z;
    o[3] = (xv.w - mu) * rs * gg.w + bb.w;
    uint16_t h[4], l[4];
#pragma unroll
    for (int e = 0; e < 4; e++) {
        h[e] = f2h(o[e]);
        l[e] = f2h(o[e] - h2f(h[e]));
    }
    const size_t vi = (size_t)n * 256 + tid;
    ((uint2*)yhi)[vi] = make_uint2((uint32_t)h[0] | ((uint32_t)h[1] << 16),
                                   (uint32_t)h[2] | ((uint32_t)h[3] << 16));
    ((uint2*)ylo)[vi] = make_uint2((uint32_t)l[0] | ((uint32_t)l[1] << 16),
                                   (uint32_t)l[2] | ((uint32_t)l[3] << 16));
}

// ---------------- fp32 -> fp16 single convert ------------------------------
__global__ void convh_kernel(const float* __restrict__ src, uint16_t* __restrict__ dst, int n4) {
    const int i0 = (blockIdx.x * 256 + threadIdx.x) * 4;
    if (i0 + 3 < n4) {
        float4 v[4];
#pragma unroll
        for (int j = 0; j < 4; j++) v[j] = ((const float4*)src)[i0 + j];
#pragma unroll
        for (int j = 0; j < 4; j++) {
            ((uint2*)dst)[i0 + j] = make_uint2(
                (uint32_t)f2h(v[j].x) | ((uint32_t)f2h(v[j].y) << 16),
                (uint32_t)f2h(v[j].z) | ((uint32_t)f2h(v[j].w) << 16));
        }
    } else {
        for (int j = 0; j < 4 && i0 + j < n4; j++) {
            const float4 v = ((const float4*)src)[i0 + j];
            ((uint2*)dst)[i0 + j] = make_uint2(
                (uint32_t)f2h(v.x) | ((uint32_t)f2h(v.y) << 16),
                (uint32_t)f2h(v.z) | ((uint32_t)f2h(v.w) << 16));
        }
    }
}

__global__ void convh3_kernel(const float* __restrict__ s0, const float* __restrict__ s1,
                              const float* __restrict__ s2,
                              uint16_t* __restrict__ dst, int n4each) {
    const int i = blockIdx.x * 256 + threadIdx.x;
    if (i >= 3 * n4each) return;
    const float* src;
    int j;
    if (i < n4each) { src = s0; j = i; }
    else if (i < 2 * n4each) { src = s1; j = i - n4each; }
    else { src = s2; j = i - 2 * n4each; }
    const float4 v = ((const float4*)src)[j];
    ((uint2*)dst)[i] = make_uint2((uint32_t)f2h(v.x) | ((uint32_t)f2h(v.y) << 16),
                                  (uint32_t)f2h(v.z) | ((uint32_t)f2h(v.w) << 16));
}

// ---------------- postproc -------------------------------------------------
__global__ void postproc_kernel(const float* __restrict__ wgw, const float* __restrict__ bgw,
                                const float* __restrict__ wgf, const float* __restrict__ bgf) {
    __shared__ float red[4][8];
    const int n = blockIdx.x;
    const int i = threadIdx.x;
    const size_t off = (size_t)n * KM + i;
    const float kv = g_k[off];
    const float qv = g_q[off];
    const size_t vi = (size_t)n * 256 + i;
    const uint2 hx = ((const uint2*)g_xn_hi)[vi];
    const uint2 lx = ((const uint2*)g_xn_lo)[vi];
    float xr[4];
    xr[0] = h2f((uint16_t)hx.x) + h2f((uint16_t)lx.x);
    xr[1] = h2f((uint16_t)(hx.x >> 16)) + h2f((uint16_t)(lx.x >> 16));
    xr[2] = h2f((uint16_t)hx.y) + h2f((uint16_t)lx.y);
    xr[3] = h2f((uint16_t)(hx.y >> 16)) + h2f((uint16_t)(lx.y >> 16));
    const float4 wg = ((const float4*)wgw)[i];
    const float4 wf = ((const float4*)wgf)[i];
    float dg = xr[0] * wg.x + xr[1] * wg.y + xr[2] * wg.z + xr[3] * wg.w;
    float df = xr[0] * wf.x + xr[1] * wf.y + xr[2] * wf.z + xr[3] * wf.w;
    float sk = warp_sum(kv * kv);
    float sq = warp_sum(qv * qv);
    dg = warp_sum(dg);
    df = warp_sum(df);
    const int wid = i >> 5, lane = i & 31;
    if (lane == 0) { red[0][wid] = sk; red[1][wid] = sq; red[2][wid] = dg; red[3][wid] = df; }
    __syncthreads();
    float tk = 0.f, tq = 0.f, tg = 0.f, tf = 0.f;
#pragma unroll
    for (int w = 0; w < 8; w++) { tk += red[0][w]; tq += red[1][w]; tg += red[2][w]; tf += red[3][w]; }
    const float kn = fmaxf(sqrtf(tk), 1e-12f);
    const float qn = fmaxf(sqrtf(tq), 1e-12f);
    g_k[off] = kv / kn;
    g_q[off] = qv / qn;
    if (i == 0) {
        g_beta[n]  = 1.0f / (1.0f + expf(-(tg + bgw[0])));
        g_decay[n] = 1.0f / (1.0f + expf(-(tf + bgf[0])));
    }
}

// ---------------- chunked scan --------------------------------------------
__global__ void chunkprod_kernel() {
    __shared__ float red[8];
    const int b = blockIdx.x >> 3;
    const int c = blockIdx.x & 7;
    const int tid = threadIdx.x;
    float d = g_decay[(size_t)b * KS + c * KL + tid];
#pragma unroll
    for (int o = 16; o; o >>= 1) d *= __shfl_xor_sync(0xffffffffu, d, o);
    if ((tid & 31) == 0) red[tid >> 5] = d;
    __syncthreads();
    if (tid == 0) {
        float p = 1.f;
#pragma unroll
        for (int w = 0; w < 8; w++) p *= red[w];
        g_dprod[b * KC + c] = p;
    }
}

__global__ void scanA_kernel() {
    const int blk = blockIdx.x;
    const int c = blk >> 7;
    const int rem = blk & 127;
    const int b = rem >> 5;
    const int i = ((rem & 31) << 3) + (threadIdx.x >> 5);
    const int lane = threadIdx.x & 31;
    const int t0 = c * KL;

    const float* kb = g_k + ((size_t)b * KS + t0) * KM + lane * 8;
    const float* vb = g_v + ((size_t)b * KS + t0) * KM + i;
    const float* bb = g_beta  + (size_t)b * KS + t0;
    const float* db = g_decay + (size_t)b * KS + t0;

    float m[8] = {0.f, 0.f, 0.f, 0.f, 0.f, 0.f, 0.f, 0.f};

    float4 k0a = *(const float4*)(kb),      k0c = *(const float4*)(kb + 4);
    float4 k1a = *(const float4*)(kb + KM), k1c = *(const float4*)(kb + KM + 4);

    for (int tt = 0; tt < KL; tt += 2) {
        const float4 ck0a = k0a, ck0c = k0c, ck1a = k1a, ck1c = k1c;
        const float vv0 = vb[(size_t)tt * KM];
        const float vv1 = vb[(size_t)(tt + 1) * KM];
        const float bt0 = bb[tt], bt1 = bb[tt + 1];
        const float dt0 = db[tt], dt1 = db[tt + 1];
        if (tt + 2 < KL) {
            const float* kn = kb + (size_t)(tt + 2) * KM;
            k0a = *(const float4*)(kn);       k0c = *(const float4*)(kn + 4);
            k1a = *(const float4*)(kn + KM);  k1c = *(const float4*)(kn + KM + 4);
        }
        const float c0 = bt0 * vv0;
        m[0] = dt0*m[0] + c0*ck0a.x;  m[1] = dt0*m[1] + c0*ck0a.y;
        m[2] = dt0*m[2] + c0*ck0a.z;  m[3] = dt0*m[3] + c0*ck0a.w;
        m[4] = dt0*m[4] + c0*ck0c.x;  m[5] = dt0*m[5] + c0*ck0c.y;
        m[6] = dt0*m[6] + c0*ck0c.z;  m[7] = dt0*m[7] + c0*ck0c.w;
        const float c1 = bt1 * vv1;
        m[0] = dt1*m[0] + c1*ck1a.x;  m[1] = dt1*m[1] + c1*ck1a.y;
        m[2] = dt1*m[2] + c1*ck1a.z;  m[3] = dt1*m[3] + c1*ck1a.w;
        m[4] = dt1*m[4] + c1*ck1c.x;  m[5] = dt1*m[5] + c1*ck1c.y;
        m[6] = dt1*m[6] + c1*ck1c.z;  m[7] = dt1*m[7] + c1*ck1c.w;
    }
    const size_t dbase = ((((size_t)c * KB + b) * KM + i) * KM) + lane * 8;
    *(float4*)(g_delta + dbase)     = make_float4(m[0], m[1], m[2], m[3]);
    *(float4*)(g_delta + dbase + 4) = make_float4(m[4], m[5], m[6], m[7]);
}

__global__ void scanB_kernel(const float* __restrict__ mem0, float* __restrict__ mem_out) {
    const int b = blockIdx.x >> 8;
    const int i = blockIdx.x & 255;
    const int j = threadIdx.x;
    const size_t base = ((size_t)b * KM + i) * KM + j;
    float m = mem0[base];
#pragma unroll
    for (int c = 0; c < KC; c++) {
        const size_t idx = ((((size_t)c * KB + b) * KM + i) * KM) + j;
        g_mstart[idx] = m;
        m = g_dprod[b * KC + c] * m + g_delta[idx];
    }
    mem_out[base] = m;
}

__global__ void scanC_kernel() {
    const int blk = blockIdx.x;
    const int c = blk >> 7;
    const int rem = blk & 127;
    const int b = rem >> 5;
    const int i = ((rem & 31) << 3) + (threadIdx.x >> 5);
    const int lane = threadIdx.x & 31;
    const int t0 = c * KL;

    const size_t sbase = ((((size_t)c * KB + b) * KM + i) * KM) + lane * 8;
    float m[8];
    { float4 a = *(const float4*)(g_mstart + sbase);
      float4 cc = *(const float4*)(g_mstart + sbase + 4);
      m[0]=a.x; m[1]=a.y; m[2]=a.z; m[3]=a.w; m[4]=cc.x; m[5]=cc.y; m[6]=cc.z; m[7]=cc.w; }

    const float* kb = g_k + ((size_t)b * KS + t0) * KM + lane * 8;
    const float* qb = g_q + ((size_t)b * KS + t0) * KM + lane * 8;
    const float* vb = g_v + ((size_t)b * KS + t0) * KM + i;
    const float* bb = g_beta  + (size_t)b * KS + t0;
    const float* db = g_decay + (size_t)b * KS + t0;
    uint16_t* ro = g_ro + ((size_t)b * KS + t0) * KM + i;

    float4 q0a = *(const float4*)(qb),            q0c = *(const float4*)(qb + 4);
    float4 k0a = *(const float4*)(kb),            k0c = *(const float4*)(kb + 4);
    float4 q1a = *(const float4*)(qb + KM),       q1c = *(const float4*)(qb + KM + 4);
    float4 k1a = *(const float4*)(kb + KM),       k1c = *(const float4*)(kb + KM + 4);

    float pp0 = 0.f, pp1 = 0.f;

    for (int tt = 0; tt < KL; tt += 2) {
        const float4 cq0a = q0a, cq0c = q0c, ck0a = k0a, ck0c = k0c;
        const float4 cq1a = q1a, cq1c = q1c, ck1a = k1a, ck1c = k1c;
        const float vv0 = vb[(size_t)tt * KM];
        const float vv1 = vb[(size_t)(tt + 1) * KM];
        const float bt0 = bb[tt], bt1 = bb[tt + 1];
        const float dt0 = db[tt], dt1 = db[tt + 1];
        if (tt + 2 < KL) {
            const float* qn = qb + (size_t)(tt + 2) * KM;
            const float* kn = kb + (size_t)(tt + 2) * KM;
            q0a = *(const float4*)(qn);       q0c = *(const float4*)(qn + 4);
            k0a = *(const float4*)(kn);       k0c = *(const float4*)(kn + 4);
            q1a = *(const float4*)(qn + KM);  q1c = *(const float4*)(qn + KM + 4);
            k1a = *(const float4*)(kn + KM);  k1c = *(const float4*)(kn + KM + 4);
        }
        float pl0 = m[0]*cq0a.x + m[1]*cq0a.y + m[2]*cq0a.z + m[3]*cq0a.w
                  + m[4]*cq0c.x + m[5]*cq0c.y + m[6]*cq0c.z + m[7]*cq0c.w;
        const float c0 = bt0 * vv0;
        m[0] = dt0*m[0] + c0*ck0a.x;  m[1] = dt0*m[1] + c0*ck0a.y;
        m[2] = dt0*m[2] + c0*ck0a.z;  m[3] = dt0*m[3] + c0*ck0a.w;
        m[4] = dt0*m[4] + c0*ck0c.x;  m[5] = dt0*m[5] + c0*ck0c.y;
        m[6] = dt0*m[6] + c0*ck0c.z;  m[7] = dt0*m[7] + c0*ck0c.w;
        float pl1 = m[0]*cq1a.x + m[1]*cq1a.y + m[2]*cq1a.z + m[3]*cq1a.w
                  + m[4]*cq1c.x + m[5]*cq1c.y + m[6]*cq1c.z + m[7]*cq1c.w;
        const float c1 = bt1 * vv1;
#pragma unroll
        for (int o = 16; o; o >>= 1) {
            pp0 += __shfl_xor_sync(0xffffffffu, pp0, o);
            pp1 += __shfl_xor_sync(0xffffffffu, pp1, o);
        }
        m[0] = dt1*m[0] + c1*ck1a.x;  m[1] = dt1*m[1] + c1*ck1a.y;
        m[2] = dt1*m[2] + c1*ck1a.z;  m[3] = dt1*m[3] + c1*ck1a.w;
        m[4] = dt1*m[4] + c1*ck1c.x;  m[5] = dt1*m[5] + c1*ck1c.y;
        m[6] = dt1*m[6] + c1*ck1c.z;  m[7] = dt1*m[7] + c1*ck1c.w;
        if (lane == 0 && tt > 0) {
            ro[(size_t)(tt - 2) * KM] = f2h(pp0);
            ro[(size_t)(tt - 1) * KM] = f2h(pp1);
        }
        pp0 = pl0;
        pp1 = pl1;
    }
#pragma unroll
    for (int o = 16; o; o >>= 1) {
        pp0 += __shfl_xor_sync(0xffffffffu, pp0, o);
        pp1 += __shfl_xor_sync(0xffffffffu, pp1, o);
    }
    if (lane == 0) {
        ro[(size_t)(KL - 2) * KM] = f2h(pp0);
        ro[(size_t)(KL - 1) * KM] = f2h(pp1);
    }
}

// ---------------- GEMM geometry ---------------------------------------------
#define ROWE 40
#define TSZ  (128 * ROWE * 2)

// ---------------- fp16x2 fused-term GEMM (kqv, BK=32) -----------------------
#define F2STAGE (3 * TSZ)
#define F2SMEM  (2 * F2STAGE)   // 61440

__global__ void __launch_bounds__(128, 3)
gemm_kqv(const uint16_t* __restrict__ Ahi, const uint16_t* __restrict__ Alo,
         const uint16_t* __restrict__ B,
         float* __restrict__ Ok, float* __restrict__ Oq, float* __restrict__ Ov,
         const float* __restrict__ bk, const float* __restrict__ bq, const float* __restrict__ bv,
         int K) {
    extern __shared__ __align__(16) uint8_t smem[];
    const uint32_t sm0 = s2u(smem);

    const int tid = threadIdx.x;
    const int wid = tid >> 5;
    const int lane = tid & 31;
    const int warp_m = wid >> 1;
    const int warp_n = wid & 1;

    const int row0 = blockIdx.y * 128;
    const int col0 = blockIdx.x * 128;
    const int kcs = K >> 5;

    auto load_stage = [&](int chunk, int buf) {
        const int k0 = chunk << 5;
        const uint32_t s0 = sm0 + buf * F2STAGE;
#pragma unroll
        for (int i = 0; i < 4; i++) {
            const int idx = tid + i * 128;
            const int row = idx >> 2, c = idx & 3;
            const uint32_t so = (uint32_t)(row * ROWE) * 2 + c * 16;
            cp16(s0 + so,           Ahi + (size_t)(row0 + row) * K + k0 + c * 8);
            cp16(s0 + TSZ + so,     Alo + (size_t)(row0 + row) * K + k0 + c * 8);
            cp16(s0 + 2 * TSZ + so, B   + (size_t)(col0 + row) * K + k0 + c * 8);
        }
    };

    float acc[4][8][4];
#pragma unroll
    for (int mt = 0; mt < 4; mt++)
#pragma unroll
        for (int nt = 0; nt < 8; nt++)
#pragma unroll
            for (int e = 0; e < 4; e++) acc[mt][nt][e] = 0.f;

    const int a_row = warp_m * 64 + (lane & 15);
    const int a_col8 = (lane >> 4) * 8;
    const int b_local = lane & 7;
    const int b_sel = lane >> 3;
    const int b_nrow = warp_n * 64 + ((b_sel >> 1) & 1) * 8 + b_local;
    const int b_k8 = (b_sel & 1) * 8;

    load_stage(0, 0);
    cp_commit();

    for (int it = 0; it < kcs; it++) {
        const int buf = it & 1;
        cp_wait<0>();
        __syncthreads();
        if (it + 1 < kcs) { load_stage(it + 1, 1 - buf); cp_commit(); }

        const uint32_t sah = sm0 + buf * F2STAGE;
        const uint32_t sal = sah + TSZ;
        const uint32_t sb  = sah + 2 * TSZ;
#pragma unroll
        for (int j = 0; j < 2; j++) {
            uint32_t b[8][2];
#pragma unroll
            for (int nt2 = 0; nt2 < 4; nt2++) {
                const uint32_t addr = sb + (uint32_t)((b_nrow + nt2 * 16) * ROWE + j * 16 + b_k8) * 2;
                uint32_t r0, r1, r2, r3;
                ldsm_x4(r0, r1, r2, r3, addr);
                b[nt2 * 2][0] = r0; b[nt2 * 2][1] = r1;
                b[nt2 * 2 + 1][0] = r2; b[nt2 * 2 + 1][1] = r3;
            }
            uint32_t a[4][4];
#pragma unroll
            for (int mt = 0; mt < 4; mt++) {
                const uint32_t addr = sah + (uint32_t)((a_row + mt * 16) * ROWE + j * 16 + a_col8) * 2;
                ldsm_x4(a[mt][0], a[mt][1], a[mt][2], a[mt][3], addr);
            }
#pragma unroll
            for (int mt = 0; mt < 4; mt++)
#pragma unroll
                for (int nt = 0; nt < 8; nt++)
                    mma_fp16(acc[mt][nt][0], acc[mt][nt][1], acc[mt][nt][2], acc[mt][nt][3],
                             a[mt][0], a[mt][1], a[mt][2], a[mt][3], b[nt][0], b[nt][1]);
#pragma unroll
            for (int mt = 0; mt < 4; mt++) {
                const uint32_t addr = sal + (uint32_t)((a_row + mt * 16) * ROWE + j * 16 + a_col8) * 2;
                ldsm_x4(a[mt][0], a[mt][1], a[mt][2], a[mt][3], addr);
            }
#pragma unroll
            for (int mt = 0; mt < 4; mt++)
#pragma unroll
                for (int nt = 0; nt < 8; nt++)
                    mma_fp16(acc[mt][nt][0], acc[mt][nt][1], acc[mt][nt][2], acc[mt][nt][3],
                             a[mt][0], a[mt][1], a[mt][2], a[mt][3], b[nt][0], b[nt][1]);
        }
    }

    const int er = lane >> 2;
    const int ec = (lane & 3) * 2;

    const int seg = blockIdx.x >> 1;
    const int segoff = (blockIdx.x & 1) * 128;
    const float* bseg = (seg == 1) ? bq : (seg == 2) ? bv : bk;
    float* oseg = (seg == 1) ? Oq : (seg == 2) ? Ov : Ok;
    const bool do_tanh = (seg == 2);

#pragma unroll
    for (int nt = 0; nt < 8; nt++) {
        const int clt = warp_n * 64 + nt * 8 + ec;
        const int cl = segoff + clt;
        const float b0 = __ldg(bseg + cl);
        const float b1 = __ldg(bseg + cl + 1);
#pragma unroll
        for (int mt = 0; mt < 4; mt++) {
            const int rl = row0 + warp_m * 64 + mt * 16 + er;
#pragma unroll
            for (int half = 0; half < 2; half++) {
                const size_t r = (size_t)(rl + half * 8);
                float v0 = acc[mt][nt][half * 2 + 0] + b0;
                float v1 = acc[mt][nt][half * 2 + 1] + b1;
                if (do_tanh) { v0 = tanhf(v0); v1 = tanhf(v1); }
                *(float2*)(oseg + r * KM + cl) = make_float2(v0, v1);
            }
        }
    }
}

// ---------------- fp16x1 single-term GEMM (BK=32, 3-stage ring) -------------
// EPI: 2 = bias+residual->fp32; 3 = bias+gelu->fp16; 4 = raw partial (split-K)
#define F1STAGE (2 * TSZ)
#define F1SMEM  (3 * F1STAGE)   // 61440

template <int EPI>
__global__ void __launch_bounds__(128, 3)
gemm1t(const uint16_t* __restrict__ A, const uint16_t* __restrict__ B,
       const float* __restrict__ bias, const float* __restrict__ res,
       float* __restrict__ Cf, uint16_t* __restrict__ C16, float* __restrict__ Part,
       int Kstride, int klen, int N) {
    extern __shared__ __align__(16) uint8_t smem[];
    const uint32_t sm0 = s2u(smem);

    const int tid = threadIdx.x;
    const int wid = tid >> 5;
    const int lane = tid & 31;
    const int warp_m = wid >> 1;
    const int warp_n = wid & 1;

    const int row0 = blockIdx.y * 128;
    const int col0 = blockIdx.x * 128;
    const int koff = blockIdx.z * klen;
    const int kcs = klen >> 5;

    auto load_stage = [&](int chunk, int buf) {
        const int k0 = koff + (chunk << 5);
        const uint32_t sa = sm0 + buf * F1STAGE;
        const uint32_t sb = sa + TSZ;
#pragma unroll
        for (int i = 0; i < 4; i++) {
            const int idx = tid + i * 128;
            const int row = idx >> 2, c = idx & 3;
            cp16(sa + (uint32_t)(row * ROWE) * 2 + c * 16,
                 A + (size_t)(row0 + row) * Kstride + k0 + c * 8);
            cp16(sb + (uint32_t)(row * ROWE) * 2 + c * 16,
                 B + (size_t)(col0 + row) * Kstride + k0 + c * 8);
        }
    };

    float acc[4][8][4];
#pragma unroll
    for (int mt = 0; mt < 4; mt++)
#pragma unroll
        for (int nt = 0; nt < 8; nt++)
#pragma unroll
            for (int e = 0; e < 4; e++) acc[mt][nt][e] = 0.f;

    const int a_row = warp_m * 64 + (lane & 15);
    const int a_col8 = (lane >> 4) * 8;
    const int b_local = lane & 7;
    const int b_sel = lane >> 3;
    const int b_nrow = warp_n * 64 + ((b_sel >> 1) & 1) * 8 + b_local;
    const int b_k8 = (b_sel & 1) * 8;

#pragma unroll
    for (int s = 0; s < 2; s++) { load_stage(s, s); cp_commit(); }

    for (int it = 0; it < kcs; it++) {
        const int buf = it % 3;
        cp_wait<1>();
        __syncthreads();
        if (it + 2 < kcs) load_stage(it + 2, (it + 2) % 3);
        cp_commit();

        const uint32_t sa = sm0 + buf * F1STAGE;
        const uint32_t sb = sa + TSZ;
#pragma unroll
        for (int j = 0; j < 2; j++) {
            uint32_t a[4][4];
#pragma unroll
            for (int mt = 0; mt < 4; mt++) {
                const uint32_t addr = sa + (uint32_t)((a_row + mt * 16) * ROWE + j * 16 + a_col8) * 2;
                ldsm_x4(a[mt][0], a[mt][1], a[mt][2], a[mt][3], addr);
            }
            uint32_t b[8][2];
#pragma unroll
            for (int nt2 = 0; nt2 < 4; nt2++) {
                const uint32_t addr = sb + (uint32_t)((b_nrow + nt2 * 16) * ROWE + j * 16 + b_k8) * 2;
                uint32_t r0, r1, r2, r3;
                ldsm_x4(r0, r1, r2, r3, addr);
                b[nt2 * 2][0] = r0; b[nt2 * 2][1] = r1;
                b[nt2 * 2 + 1][0] = r2; b[nt2 * 2 + 1][1] = r3;
            }
#pragma unroll
            for (int mt = 0; mt < 4; mt++)
#pragma unroll
                for (int nt = 0; nt < 8; nt++)
                    mma_fp16(acc[mt][nt][0], acc[mt][nt][1], acc[mt][nt][2], acc[mt][nt][3],
                             a[mt][0], a[mt][1], a[mt][2], a[mt][3], b[nt][0], b[nt][1]);
        }
    }

    const int er = lane >> 2;
    const int ec = (lane & 3) * 2;
    float* part = (EPI == 4) ? Part + (size_t)blockIdx.z * KT * KE : nullptr;

#pragma unroll
    for (int nt = 0; nt < 8; nt++) {
        const int c = col0 + warp_n * 64 + nt * 8 + ec;
        const float b0 = (EPI == 4) ? 0.f : __ldg(bias + c);
        const float b1 = (EPI == 4) ? 0.f : __ldg(bias + c + 1);
#pragma unroll
        for (int mt = 0; mt < 4; mt++) {
            const int rl = row0 + warp_m * 64 + mt * 16 + er;
#pragma unroll
            for (int half = 0; half < 2; half++) {
                const size_t r = (size_t)(rl + half * 8);
                float v0 = acc[mt][nt][half * 2 + 0] + b0;
                float v1 = acc[mt][nt][half * 2 + 1] + b1;
                if (EPI == 2) {
                    const float2 rv = *(const float2*)(res + r * N + c);
                    v0 += rv.x; v1 += rv.y;
                    *(float2*)(Cf + r * N + c) = make_float2(v0, v1);
                } else if (EPI == 3) {
                    v0 = gelu_exact(v0); v1 = gelu_exact(v1);
                    *(uint32_t*)(C16 + r * N + c) = (uint32_t)f2h(v0) | ((uint32_t)f2h(v1) << 16);
                } else {
                    *(float2*)(part + r * N + c) = make_float2(v0, v1);
                }
            }
        }
    }
}

// ---------------- split-K reduce: out = p0 + p1 + bias + x2 ------------------
__global__ void reduce_kernel(const float* __restrict__ x2, const float* __restrict__ bias,
                              float* __restrict__ out) {
    const size_t i = (size_t)blockIdx.x * 256 + threadIdx.x;   // float4 index
    const int c4 = (int)(i & (KE / 4 - 1));
    const float4 bv = ((const float4*)bias)[c4];
    float4 s = ((const float4*)g_part)[i];
    const float4 p1 = ((const float4*)(g_part + (size_t)KT * KE))[i];
    const float4 xv = ((const float4*)x2)[i];
    s.x = s.x + p1.x + xv.x + bv.x;
    s.y = s.y + p1.y + xv.y + bv.y;
    s.z = s.z + p1.z + xv.z + bv.z;
    s.w = s.w + p1.w + xv.w + bv.w;
    ((float4*)out)[i] = s;
}

// ---------------- launch ----------------
extern "C" void kernel_launch(void* const* d_in, const int* in_sizes, int n_in,
                              void* d_out, int out_size) {
    (void)in_sizes; (void)n_in; (void)out_size;
    const float* x      = (const float*)d_in[0];
    const float* memory = (const float*)d_in[1];
    const float* w_k    = (const float*)d_in[2];
    const float* b_k    = (const float*)d_in[3];
    const float* w_q    = (const float*)d_in[4];
    const float* b_q    = (const float*)d_in[5];
    const float* w_v    = (const float*)d_in[6];
    const float* b_v    = (const float*)d_in[7];
    const float* w_out  = (const float*)d_in[8];
    const float* b_out  = (const float*)d_in[9];
    const float* w_gw   = (const float*)d_in[10];
    const float* b_gw   = (const float*)d_in[11];
    const float* w_gf   = (const float*)d_in[12];
    const float* b_gf   = (const float*)d_in[13];
    const float* ln1_g  = (const float*)d_in[14];
    const float* ln1_b  = (const float*)d_in[15];
    const float* ln2_g  = (const float*)d_in[16];
    const float* ln2_b  = (const float*)d_in[17];
    const float* w_f1   = (const float*)d_in[18];
    const float* b_f1   = (const float*)d_in[19];
    const float* w_f2   = (const float*)d_in[20];
    const float* b_f2   = (const float*)d_in[21];

    float* out_x   = (float*)d_out;
    float* out_mem = out_x + (size_t)KT * KE;

    float *p_k, *p_q, *p_v, *p_x2, *p_part;
    uint16_t *p_xnh, *p_xnl, *p_ro, *p_f1;
    uint16_t *p_wkqv, *p_wo, *p_wf1, *p_wf2;
    cudaGetSymbolAddress((void**)&p_k,    g_k);
    cudaGetSymbolAddress((void**)&p_q,    g_q);
    cudaGetSymbolAddress((void**)&p_v,    g_v);
    cudaGetSymbolAddress((void**)&p_x2,   g_x2);
    cudaGetSymbolAddress((void**)&p_part, g_part);
    cudaGetSymbolAddress((void**)&p_xnh,  g_xn_hi);
    cudaGetSymbolAddress((void**)&p_xnl,  g_xn_lo);
    cudaGetSymbolAddress((void**)&p_ro,   g_ro);
    cudaGetSymbolAddress((void**)&p_f1,   g_f1);
    cudaGetSymbolAddress((void**)&p_wkqv, g_wkqv_h);
    cudaGetSymbolAddress((void**)&p_wo,   g_wo_h);
    cudaGetSymbolAddress((void**)&p_wf1,  g_wf1_h);
    cudaGetSymbolAddress((void**)&p_wf2,  g_wf2_h);

    cudaFuncSetAttribute(gemm_kqv,  cudaFuncAttributeMaxDynamicSharedMemorySize, F2SMEM);
    cudaFuncSetAttribute(gemm1t<2>, cudaFuncAttributeMaxDynamicSharedMemorySize, F1SMEM);
    cudaFuncSetAttribute(gemm1t<3>, cudaFuncAttributeMaxDynamicSharedMemorySize, F1SMEM);
    cudaFuncSetAttribute(gemm1t<4>, cudaFuncAttributeMaxDynamicSharedMemorySize, F1SMEM);

    // launch order: ncu captures OUR index 3 -> kqv GEMM (probe)
    // 0) fused convert of w_k|w_q|w_v -> fp16
    convh3_kernel<<<768, 256>>>(w_k, w_q, w_v, p_wkqv, KM*KE/4);
    // 1) LN1 -> xn fp16 hi/lo
    ln_kernel<<<KT, 256>>>(x, ln1_g, ln1_b, p_xnh, p_xnl);
    // 2) convert w_out -> fp16
    convh_kernel<<<(KE*KM/4 + 1023)/1024, 256>>>(w_out, p_wo, KE*KM/4);
    // 3) fused kqv GEMM (fp16x2 fused-term)  [profiled: clock-hypothesis test]
    gemm_kqv<<<dim3(6, KT/128), 128, F2SMEM>>>(
        p_xnh, p_xnl, p_wkqv, p_k, p_q, p_v, b_k, b_q, b_v, KE);
    // 4-5) convert FFN weights -> fp16
    convh_kernel<<<(KF*KE/4 + 1023)/1024, 256>>>(w_f1, p_wf1, KF*KE/4);
    convh_kernel<<<(KE*KF/4 + 1023)/1024, 256>>>(w_f2, p_wf2, KE*KF/4);
    // 6) l2norm + gates
    postproc_kernel<<<KT, 256>>>(w_gw, b_gw, w_gf, b_gf);
    // 7) chunk decay products
    chunkprod_kernel<<<KB * KC, KL>>>();
    // 8) scan pass A
    scanA_kernel<<<KC * KB * 32, 256>>>();
    // 9) scan pass B (+ final memory output)
    scanB_kernel<<<KB * KM, 256>>>(memory, out_mem);
    // 10) scan pass C (readouts -> fp16 single)
    scanC_kernel<<<KC * KB * 32, 256>>>();
    // 11) out projection + residual(x) -> x2 (fp16x1)
    gemm1t<2><<<dim3(KE/128, KT/128), 128, F1SMEM>>>(
        p_ro, p_wo, b_out, x, p_x2, nullptr, nullptr, KM, KM, KE);
    // 12) LN2 -> xn fp16 hi/lo (FFN1 reads hi only)
    ln_kernel<<<KT, 256>>>(p_x2, ln2_g, ln2_b, p_xnh, p_xnl);
    // 13) FFN1 + GELU -> f1 fp16 single (fp16x1)
    gemm1t<3><<<dim3(KF/128, KT/128), 128, F1SMEM>>>(
        p_xnh, p_wf1, b_f1, nullptr, nullptr, p_f1, nullptr, KE, KE, KF);
    // 14) FFN2 split-K=2 -> partials (fp16x1, unchanged BK=32 kernel)
    gemm1t<4><<<dim3(KE/128, KT/128, KSK), 128, F1SMEM>>>(
        p_f1, p_wf2, nullptr, nullptr, nullptr, nullptr, p_part, KF, KF/KSK, KE);
    // 15) reduce partials + bias + residual(x2) -> out
    reduce_kernel<<<KT * KE / 4 / 256, 256>>>(p_x2, b_f2, out_x);
}

// round 17
// speedup vs baseline: 1.5481x; 1.0119x over previous
#include <cuda_runtime.h>
#include <cuda_bf16.h>
#include <cuda_fp16.h>
#include <math.h>
#include <stdint.h>

#define KB 4
#define KS 2048
#define KE 1024
#define KM 256
#define KF (4 * KE)
#define KT (KB * KS)   // 8192 tokens
#define KC 8           // scan chunks
#define KL (KS / KC)   // 256 steps per chunk
#define KSK 2          // FFN2 split-K factor

// ---------------- scratch (device globals; no runtime allocation) ----------
__device__ __align__(16) float g_k [(size_t)KT * KM];
__device__ __align__(16) float g_q [(size_t)KT * KM];
__device__ __align__(16) float g_v [(size_t)KT * KM];
__device__ float g_beta [KT];
__device__ float g_decay[KT];
__device__ __align__(16) float g_x2[(size_t)KT * KE];
__device__ __align__(16) float g_part[(size_t)KSK * KT * KE];

__device__ __align__(16) float g_delta [(size_t)KC * KB * KM * KM];
__device__ __align__(16) float g_mstart[(size_t)KC * KB * KM * KM];
__device__ float g_dprod[KB * KC];

// fp16 scratch (raw u16)
__device__ __align__(16) uint16_t g_xn_hi[(size_t)KT * KE];
__device__ __align__(16) uint16_t g_xn_lo[(size_t)KT * KE];
__device__ __align__(16) uint16_t g_ro  [(size_t)KT * KM];
__device__ __align__(16) uint16_t g_f1  [(size_t)KT * KF];

__device__ __align__(16) uint16_t g_wkqv_h[(size_t)3 * KM * KE];
__device__ __align__(16) uint16_t g_wo_h[KE * KM];
__device__ __align__(16) uint16_t g_wf1_h[(size_t)KF * KE];
__device__ __align__(16) uint16_t g_wf2_h[(size_t)KE * KF];

// ---------------- small helpers ----------------
__device__ __forceinline__ float warp_sum(float v) {
#pragma unroll
    for (int o = 16; o; o >>= 1) v += __shfl_xor_sync(0xffffffffu, v, o);
    return v;
}
__device__ __forceinline__ float gelu_exact(float v) {
    return 0.5f * v * (1.0f + erff(v * 0.70710678118654752f));
}
__device__ __forceinline__ uint16_t f2h(float x) {
    __half h = __float2half_rn(x);
    return *reinterpret_cast<uint16_t*>(&h);
}
__device__ __forceinline__ float h2f(uint16_t u) {
    __half h = *reinterpret_cast<__half*>(&u);
    return __half2float(h);
}
__device__ __forceinline__ uint32_t s2u(const void* p) {
    uint32_t a;
    asm("{ .reg .u64 t; cvta.to.shared.u64 t, %1; cvt.u32.u64 %0, t; }" : "=r"(a) : "l"(p));
    return a;
}

// ---------------- PTX wrappers ----------------
__device__ __forceinline__ void cp16(uint32_t d, const void* g) {
    asm volatile("cp.async.cg.shared.global [%0], [%1], 16;\n" :: "r"(d), "l"(g));
}
__device__ __forceinline__ void cp_commit() { asm volatile("cp.async.commit_group;\n" ::: "memory"); }
template <int N> __device__ __forceinline__ void cp_wait() {
    asm volatile("cp.async.wait_group %0;\n" :: "n"(N) : "memory");
}
__device__ __forceinline__ void ldsm_x4(uint32_t& r0, uint32_t& r1, uint32_t& r2, uint32_t& r3,
                                        uint32_t addr) {
    asm volatile("ldmatrix.sync.aligned.m8n8.x4.shared.b16 {%0,%1,%2,%3}, [%4];"
                 : "=r"(r0), "=r"(r1), "=r"(r2), "=r"(r3) : "r"(addr));
}
__device__ __forceinline__ void mma_fp16(float& c0, float& c1, float& c2, float& c3,
                                         uint32_t a0, uint32_t a1, uint32_t a2, uint32_t a3,
                                         uint32_t b0, uint32_t b1) {
    asm volatile(
        "mma.sync.aligned.m16n8k16.row.col.f32.f16.f16.f32 "
        "{%0,%1,%2,%3}, {%4,%5,%6,%7}, {%8,%9}, {%0,%1,%2,%3};"
        : "+f"(c0), "+f"(c1), "+f"(c2), "+f"(c3)
        : "r"(a0), "r"(a1), "r"(a2), "r"(a3), "r"(b0), "r"(b1));
}

// ---------------- LayerNorm -> fp16 hi/lo ----------------------------------
__global__ void ln_kernel(const float* __restrict__ x, const float* __restrict__ g,
                          const float* __restrict__ bvec,
                          uint16_t* __restrict__ yhi, uint16_t* __restrict__ ylo) {
    __shared__ float red[2][8];
    const int n = blockIdx.x;
    const int tid = threadIdx.x;
    const float4 xv = ((const float4*)(x + (size_t)n * KE))[tid];
    float s  = xv.x + xv.y + xv.z + xv.w;
    float ss = xv.x * xv.x + xv.y * xv.y + xv.z * xv.z + xv.w * xv.w;
    s = warp_sum(s); ss = warp_sum(ss);
    const int wid = tid >> 5, lane = tid & 31;
    if (lane == 0) { red[0][wid] = s; red[1][wid] = ss; }
    __syncthreads();
    float st = 0.f, sst = 0.f;
#pragma unroll
    for (int w = 0; w < 8; w++) { st += red[0][w]; sst += red[1][w]; }
    const float mu  = st * (1.0f / KE);
    const float var = sst * (1.0f / KE) - mu * mu;
    const float rs  = rsqrtf(var + 1e-5f);
    const float4 gg = ((const float4*)g)[tid];
    const float4 bb = ((const float4*)bvec)[tid];
    float o[4];
    o[0] = (xv.x - mu) * rs * gg.x + bb.x;
    o[1] = (xv.y - mu) * rs * gg.y + bb.y;
    o[2] = (xv.z - mu) * rs * gg.z + bb.z;
    o[3] = (xv.w - mu) * rs * gg.w + bb.w;
    uint16_t h[4], l[4];
#pragma unroll
    for (int e = 0; e < 4; e++) {
        h[e] = f2h(o[e]);
        l[e] = f2h(o[e] - h2f(h[e]));
    }
    const size_t vi = (size_t)n * 256 + tid;
    ((uint2*)yhi)[vi] = make_uint2((uint32_t)h[0] | ((uint32_t)h[1] << 16),
                                   (uint32_t)h[2] | ((uint32_t)h[3] << 16));
    ((uint2*)ylo)[vi] = make_uint2((uint32_t)l[0] | ((uint32_t)l[1] << 16),
                                   (uint32_t)l[2] | ((uint32_t)l[3] << 16));
}

// ---------------- fp32 -> fp16 single convert ------------------------------
__global__ void convh_kernel(const float* __restrict__ src, uint16_t* __restrict__ dst, int n4) {
    const int i0 = (blockIdx.x * 256 + threadIdx.x) * 4;
    if (i0 + 3 < n4) {
        float4 v[4];
#pragma unroll
        for (int j = 0; j < 4; j++) v[j] = ((const float4*)src)[i0 + j];
#pragma unroll
        for (int j = 0; j < 4; j++) {
            ((uint2*)dst)[i0 + j] = make_uint2(
                (uint32_t)f2h(v[j].x) | ((uint32_t)f2h(v[j].y) << 16),
                (uint32_t)f2h(v[j].z) | ((uint32_t)f2h(v[j].w) << 16));
        }
    } else {
        for (int j = 0; j < 4 && i0 + j < n4; j++) {
            const float4 v = ((const float4*)src)[i0 + j];
            ((uint2*)dst)[i0 + j] = make_uint2(
                (uint32_t)f2h(v.x) | ((uint32_t)f2h(v.y) << 16),
                (uint32_t)f2h(v.z) | ((uint32_t)f2h(v.w) << 16));
        }
    }
}

__global__ void convh3_kernel(const float* __restrict__ s0, const float* __restrict__ s1,
                              const float* __restrict__ s2,
                              uint16_t* __restrict__ dst, int n4each) {
    const int i = blockIdx.x * 256 + threadIdx.x;
    if (i >= 3 * n4each) return;
    const float* src;
    int j;
    if (i < n4each) { src = s0; j = i; }
    else if (i < 2 * n4each) { src = s1; j = i - n4each; }
    else { src = s2; j = i - 2 * n4each; }
    const float4 v = ((const float4*)src)[j];
    ((uint2*)dst)[i] = make_uint2((uint32_t)f2h(v.x) | ((uint32_t)f2h(v.y) << 16),
                                  (uint32_t)f2h(v.z) | ((uint32_t)f2h(v.w) << 16));
}

// ---------------- postproc -------------------------------------------------
__global__ void postproc_kernel(const float* __restrict__ wgw, const float* __restrict__ bgw,
                                const float* __restrict__ wgf, const float* __restrict__ bgf) {
    __shared__ float red[4][8];
    const int n = blockIdx.x;
    const int i = threadIdx.x;
    const size_t off = (size_t)n * KM + i;
    const float kv = g_k[off];
    const float qv = g_q[off];
    const size_t vi = (size_t)n * 256 + i;
    const uint2 hx = ((const uint2*)g_xn_hi)[vi];
    const uint2 lx = ((const uint2*)g_xn_lo)[vi];
    float xr[4];
    xr[0] = h2f((uint16_t)hx.x) + h2f((uint16_t)lx.x);
    xr[1] = h2f((uint16_t)(hx.x >> 16)) + h2f((uint16_t)(lx.x >> 16));
    xr[2] = h2f((uint16_t)hx.y) + h2f((uint16_t)lx.y);
    xr[3] = h2f((uint16_t)(hx.y >> 16)) + h2f((uint16_t)(lx.y >> 16));
    const float4 wg = ((const float4*)wgw)[i];
    const float4 wf = ((const float4*)wgf)[i];
    float dg = xr[0] * wg.x + xr[1] * wg.y + xr[2] * wg.z + xr[3] * wg.w;
    float df = xr[0] * wf.x + xr[1] * wf.y + xr[2] * wf.z + xr[3] * wf.w;
    float sk = warp_sum(kv * kv);
    float sq = warp_sum(qv * qv);
    dg = warp_sum(dg);
    df = warp_sum(df);
    const int wid = i >> 5, lane = i & 31;
    if (lane == 0) { red[0][wid] = sk; red[1][wid] = sq; red[2][wid] = dg; red[3][wid] = df; }
    __syncthreads();
    float tk = 0.f, tq = 0.f, tg = 0.f, tf = 0.f;
#pragma unroll
    for (int w = 0; w < 8; w++) { tk += red[0][w]; tq += red[1][w]; tg += red[2][w]; tf += red[3][w]; }
    const float kn = fmaxf(sqrtf(tk), 1e-12f);
    const float qn = fmaxf(sqrtf(tq), 1e-12f);
    g_k[off] = kv / kn;
    g_q[off] = qv / qn;
    if (i == 0) {
        g_beta[n]  = 1.0f / (1.0f + expf(-(tg + bgw[0])));
        g_decay[n] = 1.0f / (1.0f + expf(-(tf + bgf[0])));
    }
}

// ---------------- chunked scan --------------------------------------------
__global__ void chunkprod_kernel() {
    __shared__ float red[8];
    const int b = blockIdx.x >> 3;
    const int c = blockIdx.x & 7;
    const int tid = threadIdx.x;
    float d = g_decay[(size_t)b * KS + c * KL + tid];
#pragma unroll
    for (int o = 16; o; o >>= 1) d *= __shfl_xor_sync(0xffffffffu, d, o);
    if ((tid & 31) == 0) red[tid >> 5] = d;
    __syncthreads();
    if (tid == 0) {
        float p = 1.f;
#pragma unroll
        for (int w = 0; w < 8; w++) p *= red[w];
        g_dprod[b * KC + c] = p;
    }
}

__global__ void scanA_kernel() {
    const int blk = blockIdx.x;
    const int c = blk >> 7;
    const int rem = blk & 127;
    const int b = rem >> 5;
    const int i = ((rem & 31) << 3) + (threadIdx.x >> 5);
    const int lane = threadIdx.x & 31;
    const int t0 = c * KL;

    const float* kb = g_k + ((size_t)b * KS + t0) * KM + lane * 8;
    const float* vb = g_v + ((size_t)b * KS + t0) * KM + i;
    const float* bb = g_beta  + (size_t)b * KS + t0;
    const float* db = g_decay + (size_t)b * KS + t0;

    float m[8] = {0.f, 0.f, 0.f, 0.f, 0.f, 0.f, 0.f, 0.f};

    float4 k0a = *(const float4*)(kb),      k0c = *(const float4*)(kb + 4);
    float4 k1a = *(const float4*)(kb + KM), k1c = *(const float4*)(kb + KM + 4);

    for (int tt = 0; tt < KL; tt += 2) {
        const float4 ck0a = k0a, ck0c = k0c, ck1a = k1a, ck1c = k1c;
        const float vv0 = vb[(size_t)tt * KM];
        const float vv1 = vb[(size_t)(tt + 1) * KM];
        const float bt0 = bb[tt], bt1 = bb[tt + 1];
        const float dt0 = db[tt], dt1 = db[tt + 1];
        if (tt + 2 < KL) {
            const float* kn = kb + (size_t)(tt + 2) * KM;
            k0a = *(const float4*)(kn);       k0c = *(const float4*)(kn + 4);
            k1a = *(const float4*)(kn + KM);  k1c = *(const float4*)(kn + KM + 4);
        }
        const float c0 = bt0 * vv0;
        m[0] = dt0*m[0] + c0*ck0a.x;  m[1] = dt0*m[1] + c0*ck0a.y;
        m[2] = dt0*m[2] + c0*ck0a.z;  m[3] = dt0*m[3] + c0*ck0a.w;
        m[4] = dt0*m[4] + c0*ck0c.x;  m[5] = dt0*m[5] + c0*ck0c.y;
        m[6] = dt0*m[6] + c0*ck0c.z;  m[7] = dt0*m[7] + c0*ck0c.w;
        const float c1 = bt1 * vv1;
        m[0] = dt1*m[0] + c1*ck1a.x;  m[1] = dt1*m[1] + c1*ck1a.y;
        m[2] = dt1*m[2] + c1*ck1a.z;  m[3] = dt1*m[3] + c1*ck1a.w;
        m[4] = dt1*m[4] + c1*ck1c.x;  m[5] = dt1*m[5] + c1*ck1c.y;
        m[6] = dt1*m[6] + c1*ck1c.z;  m[7] = dt1*m[7] + c1*ck1c.w;
    }
    const size_t dbase = ((((size_t)c * KB + b) * KM + i) * KM) + lane * 8;
    *(float4*)(g_delta + dbase)     = make_float4(m[0], m[1], m[2], m[3]);
    *(float4*)(g_delta + dbase + 4) = make_float4(m[4], m[5], m[6], m[7]);
}

__global__ void scanB_kernel(const float* __restrict__ mem0, float* __restrict__ mem_out) {
    const int b = blockIdx.x >> 8;
    const int i = blockIdx.x & 255;
    const int j = threadIdx.x;
    const size_t base = ((size_t)b * KM + i) * KM + j;
    float m = mem0[base];
#pragma unroll
    for (int c = 0; c < KC; c++) {
        const size_t idx = ((((size_t)c * KB + b) * KM + i) * KM) + j;
        g_mstart[idx] = m;
        m = g_dprod[b * KC + c] * m + g_delta[idx];
    }
    mem_out[base] = m;
}

__global__ void scanC_kernel() {
    const int blk = blockIdx.x;
    const int c = blk >> 7;
    const int rem = blk & 127;
    const int b = rem >> 5;
    const int i = ((rem & 31) << 3) + (threadIdx.x >> 5);
    const int lane = threadIdx.x & 31;
    const int t0 = c * KL;

    const size_t sbase = ((((size_t)c * KB + b) * KM + i) * KM) + lane * 8;
    float m[8];
    { float4 a = *(const float4*)(g_mstart + sbase);
      float4 cc = *(const float4*)(g_mstart + sbase + 4);
      m[0]=a.x; m[1]=a.y; m[2]=a.z; m[3]=a.w; m[4]=cc.x; m[5]=cc.y; m[6]=cc.z; m[7]=cc.w; }

    const float* kb = g_k + ((size_t)b * KS + t0) * KM + lane * 8;
    const float* qb = g_q + ((size_t)b * KS + t0) * KM + lane * 8;
    const float* vb = g_v + ((size_t)b * KS + t0) * KM + i;
    const float* bb = g_beta  + (size_t)b * KS + t0;
    const float* db = g_decay + (size_t)b * KS + t0;
    uint16_t* ro = g_ro + ((size_t)b * KS + t0) * KM + i;

    float4 q0a = *(const float4*)(qb),            q0c = *(const float4*)(qb + 4);
    float4 k0a = *(const float4*)(kb),            k0c = *(const float4*)(kb + 4);
    float4 q1a = *(const float4*)(qb + KM),       q1c = *(const float4*)(qb + KM + 4);
    float4 k1a = *(const float4*)(kb + KM),       k1c = *(const float4*)(kb + KM + 4);

    float pp0 = 0.f, pp1 = 0.f;

    for (int tt = 0; tt < KL; tt += 2) {
        const float4 cq0a = q0a, cq0c = q0c, ck0a = k0a, ck0c = k0c;
        const float4 cq1a = q1a, cq1c = q1c, ck1a = k1a, ck1c = k1c;
        const float vv0 = vb[(size_t)tt * KM];
        const float vv1 = vb[(size_t)(tt + 1) * KM];
        const float bt0 = bb[tt], bt1 = bb[tt + 1];
        const float dt0 = db[tt], dt1 = db[tt + 1];
        if (tt + 2 < KL) {
            const float* qn = qb + (size_t)(tt + 2) * KM;
            const float* kn = kb + (size_t)(tt + 2) * KM;
            q0a = *(const float4*)(qn);       q0c = *(const float4*)(qn + 4);
            k0a = *(const float4*)(kn);       k0c = *(const float4*)(kn + 4);
            q1a = *(const float4*)(qn + KM);  q1c = *(const float4*)(qn + KM + 4);
            k1a = *(const float4*)(kn + KM);  k1c = *(const float4*)(kn + KM + 4);
        }
        float pl0 = m[0]*cq0a.x + m[1]*cq0a.y + m[2]*cq0a.z + m[3]*cq0a.w
                  + m[4]*cq0c.x + m[5]*cq0c.y + m[6]*cq0c.z + m[7]*cq0c.w;
        const float c0 = bt0 * vv0;
        m[0] = dt0*m[0] + c0*ck0a.x;  m[1] = dt0*m[1] + c0*ck0a.y;
        m[2] = dt0*m[2] + c0*ck0a.z;  m[3] = dt0*m[3] + c0*ck0a.w;
        m[4] = dt0*m[4] + c0*ck0c.x;  m[5] = dt0*m[5] + c0*ck0c.y;
        m[6] = dt0*m[6] + c0*ck0c.z;  m[7] = dt0*m[7] + c0*ck0c.w;
        float pl1 = m[0]*cq1a.x + m[1]*cq1a.y + m[2]*cq1a.z + m[3]*cq1a.w
                  + m[4]*cq1c.x + m[5]*cq1c.y + m[6]*cq1c.z + m[7]*cq1c.w;
        const float c1 = bt1 * vv1;
#pragma unroll
        for (int o = 16; o; o >>= 1) {
            pp0 += __shfl_xor_sync(0xffffffffu, pp0, o);
            pp1 += __shfl_xor_sync(0xffffffffu, pp1, o);
        }
        m[0] = dt1*m[0] + c1*ck1a.x;  m[1] = dt1*m[1] + c1*ck1a.y;
        m[2] = dt1*m[2] + c1*ck1a.z;  m[3] = dt1*m[3] + c1*ck1a.w;
        m[4] = dt1*m[4] + c1*ck1c.x;  m[5] = dt1*m[5] + c1*ck1c.y;
        m[6] = dt1*m[6] + c1*ck1c.z;  m[7] = dt1*m[7] + c1*ck1c.w;
        if (lane == 0 && tt > 0) {
            ro[(size_t)(tt - 2) * KM] = f2h(pp0);
            ro[(size_t)(tt - 1) * KM] = f2h(pp1);
        }
        pp0 = pl0;
        pp1 = pl1;
    }
#pragma unroll
    for (int o = 16; o; o >>= 1) {
        pp0 += __shfl_xor_sync(0xffffffffu, pp0, o);
        pp1 += __shfl_xor_sync(0xffffffffu, pp1, o);
    }
    if (lane == 0) {
        ro[(size_t)(KL - 2) * KM] = f2h(pp0);
        ro[(size_t)(KL - 1) * KM] = f2h(pp1);
    }
}

// ---------------- GEMM geometry ---------------------------------------------
#define ROWE 40
#define TSZ  (128 * ROWE * 2)

// ---------------- fp16x2 fused-term GEMM (kqv, BK=32, PROBE - unchanged) ----
#define F2STAGE (3 * TSZ)
#define F2SMEM  (2 * F2STAGE)   // 61440

__global__ void __launch_bounds__(128, 3)
gemm_kqv(const uint16_t* __restrict__ Ahi, const uint16_t* __restrict__ Alo,
         const uint16_t* __restrict__ B,
         float* __restrict__ Ok, float* __restrict__ Oq, float* __restrict__ Ov,
         const float* __restrict__ bk, const float* __restrict__ bq, const float* __restrict__ bv,
         int K) {
    extern __shared__ __align__(16) uint8_t smem[];
    const uint32_t sm0 = s2u(smem);

    const int tid = threadIdx.x;
    const int wid = tid >> 5;
    const int lane = tid & 31;
    const int warp_m = wid >> 1;
    const int warp_n = wid & 1;

    const int row0 = blockIdx.y * 128;
    const int col0 = blockIdx.x * 128;
    const int kcs = K >> 5;

    auto load_stage = [&](int chunk, int buf) {
        const int k0 = chunk << 5;
        const uint32_t s0 = sm0 + buf * F2STAGE;
#pragma unroll
        for (int i = 0; i < 4; i++) {
            const int idx = tid + i * 128;
            const int row = idx >> 2, c = idx & 3;
            const uint32_t so = (uint32_t)(row * ROWE) * 2 + c * 16;
            cp16(s0 + so,           Ahi + (size_t)(row0 + row) * K + k0 + c * 8);
            cp16(s0 + TSZ + so,     Alo + (size_t)(row0 + row) * K + k0 + c * 8);
            cp16(s0 + 2 * TSZ + so, B   + (size_t)(col0 + row) * K + k0 + c * 8);
        }
    };

    float acc[4][8][4];
#pragma unroll
    for (int mt = 0; mt < 4; mt++)
#pragma unroll
        for (int nt = 0; nt < 8; nt++)
#pragma unroll
            for (int e = 0; e < 4; e++) acc[mt][nt][e] = 0.f;

    const int a_row = warp_m * 64 + (lane & 15);
    const int a_col8 = (lane >> 4) * 8;
    const int b_local = lane & 7;
    const int b_sel = lane >> 3;
    const int b_nrow = warp_n * 64 + ((b_sel >> 1) & 1) * 8 + b_local;
    const int b_k8 = (b_sel & 1) * 8;

    load_stage(0, 0);
    cp_commit();

    for (int it = 0; it < kcs; it++) {
        const int buf = it & 1;
        cp_wait<0>();
        __syncthreads();
        if (it + 1 < kcs) { load_stage(it + 1, 1 - buf); cp_commit(); }

        const uint32_t sah = sm0 + buf * F2STAGE;
        const uint32_t sal = sah + TSZ;
        const uint32_t sb  = sah + 2 * TSZ;
#pragma unroll
        for (int j = 0; j < 2; j++) {
            uint32_t b[8][2];
#pragma unroll
            for (int nt2 = 0; nt2 < 4; nt2++) {
                const uint32_t addr = sb + (uint32_t)((b_nrow + nt2 * 16) * ROWE + j * 16 + b_k8) * 2;
                uint32_t r0, r1, r2, r3;
                ldsm_x4(r0, r1, r2, r3, addr);
                b[nt2 * 2][0] = r0; b[nt2 * 2][1] = r1;
                b[nt2 * 2 + 1][0] = r2; b[nt2 * 2 + 1][1] = r3;
            }
            uint32_t a[4][4];
#pragma unroll
            for (int mt = 0; mt < 4; mt++) {
                const uint32_t addr = sah + (uint32_t)((a_row + mt * 16) * ROWE + j * 16 + a_col8) * 2;
                ldsm_x4(a[mt][0], a[mt][1], a[mt][2], a[mt][3], addr);
            }
#pragma unroll
            for (int mt = 0; mt < 4; mt++)
#pragma unroll
                for (int nt = 0; nt < 8; nt++)
                    mma_fp16(acc[mt][nt][0], acc[mt][nt][1], acc[mt][nt][2], acc[mt][nt][3],
                             a[mt][0], a[mt][1], a[mt][2], a[mt][3], b[nt][0], b[nt][1]);
#pragma unroll
            for (int mt = 0; mt < 4; mt++) {
                const uint32_t addr = sal + (uint32_t)((a_row + mt * 16) * ROWE + j * 16 + a_col8) * 2;
                ldsm_x4(a[mt][0], a[mt][1], a[mt][2], a[mt][3], addr);
            }
#pragma unroll
            for (int mt = 0; mt < 4; mt++)
#pragma unroll
                for (int nt = 0; nt < 8; nt++)
                    mma_fp16(acc[mt][nt][0], acc[mt][nt][1], acc[mt][nt][2], acc[mt][nt][3],
                             a[mt][0], a[mt][1], a[mt][2], a[mt][3], b[nt][0], b[nt][1]);
        }
    }

    const int er = lane >> 2;
    const int ec = (lane & 3) * 2;

    const int seg = blockIdx.x >> 1;
    const int segoff = (blockIdx.x & 1) * 128;
    const float* bseg = (seg == 1) ? bq : (seg == 2) ? bv : bk;
    float* oseg = (seg == 1) ? Oq : (seg == 2) ? Ov : Ok;
    const bool do_tanh = (seg == 2);

#pragma unroll
    for (int nt = 0; nt < 8; nt++) {
        const int clt = warp_n * 64 + nt * 8 + ec;
        const int cl = segoff + clt;
        const float b0 = __ldg(bseg + cl);
        const float b1 = __ldg(bseg + cl + 1);
#pragma unroll
        for (int mt = 0; mt < 4; mt++) {
            const int rl = row0 + warp_m * 64 + mt * 16 + er;
#pragma unroll
            for (int half = 0; half < 2; half++) {
                const size_t r = (size_t)(rl + half * 8);
                float v0 = acc[mt][nt][half * 2 + 0] + b0;
                float v1 = acc[mt][nt][half * 2 + 1] + b1;
                if (do_tanh) { v0 = tanhf(v0); v1 = tanhf(v1); }
                *(float2*)(oseg + r * KM + cl) = make_float2(v0, v1);
            }
        }
    }
}

// ---------------- fp16x1 single-term GEMM, BK=64, 2-stage --------------------
// EPI: 2 = bias+residual->fp32; 3 = bias+gelu->fp16; 4 = raw partial (split-K)
#define ROWE2 72
#define T64   (128 * ROWE2 * 2)     // 18432
#define G1STAGE (2 * T64)           // 36864
#define G1SMEM  (2 * G1STAGE)       // 73728

template <int EPI>
__global__ void __launch_bounds__(128, 3)
gemm1t(const uint16_t* __restrict__ A, const uint16_t* __restrict__ B,
       const float* __restrict__ bias, const float* __restrict__ res,
       float* __restrict__ Cf, uint16_t* __restrict__ C16, float* __restrict__ Part,
       int Kstride, int klen, int N) {
    extern __shared__ __align__(16) uint8_t smem[];
    const uint32_t sm0 = s2u(smem);

    const int tid = threadIdx.x;
    const int wid = tid >> 5;
    const int lane = tid & 31;
    const int warp_m = wid >> 1;
    const int warp_n = wid & 1;

    const int row0 = blockIdx.y * 128;
    const int col0 = blockIdx.x * 128;
    const int koff = blockIdx.z * klen;
    const int kcs = klen >> 6;

    auto load_stage = [&](int chunk, int buf) {
        const int k0 = koff + (chunk << 6);
        const uint32_t sa = sm0 + buf * G1STAGE;
        const uint32_t sb = sa + T64;
#pragma unroll
        for (int i = 0; i < 8; i++) {
            const int idx = tid + i * 128;        // 0..1023
            const int row = idx >> 3, c = idx & 7;
            cp16(sa + (uint32_t)(row * ROWE2) * 2 + c * 16,
                 A + (size_t)(row0 + row) * Kstride + k0 + c * 8);
            cp16(sb + (uint32_t)(row * ROWE2) * 2 + c * 16,
                 B + (size_t)(col0 + row) * Kstride + k0 + c * 8);
        }
    };

    float acc[4][8][4];
#pragma unroll
    for (int mt = 0; mt < 4; mt++)
#pragma unroll
        for (int nt = 0; nt < 8; nt++)
#pragma unroll
            for (int e = 0; e < 4; e++) acc[mt][nt][e] = 0.f;

    const int a_row = warp_m * 64 + (lane & 15);
    const int a_col8 = (lane >> 4) * 8;
    const int b_local = lane & 7;
    const int b_sel = lane >> 3;
    const int b_nrow = warp_n * 64 + ((b_sel >> 1) & 1) * 8 + b_local;
    const int b_k8 = (b_sel & 1) * 8;

    load_stage(0, 0);
    cp_commit();

    for (int it = 0; it < kcs; it++) {
        const int buf = it & 1;
        cp_wait<0>();
        __syncthreads();
        if (it + 1 < kcs) { load_stage(it + 1, 1 - buf); cp_commit(); }

        const uint32_t sa = sm0 + buf * G1STAGE;
        const uint32_t sb = sa + T64;
#pragma unroll
        for (int j = 0; j < 4; j++) {
            uint32_t a[4][4];
#pragma unroll
            for (int mt = 0; mt < 4; mt++) {
                const uint32_t addr = sa + (uint32_t)((a_row + mt * 16) * ROWE2 + j * 16 + a_col8) * 2;
                ldsm_x4(a[mt][0], a[mt][1], a[mt][2], a[mt][3], addr);
            }
            uint32_t b[8][2];
#pragma unroll
            for (int nt2 = 0; nt2 < 4; nt2++) {
                const uint32_t addr = sb + (uint32_t)((b_nrow + nt2 * 16) * ROWE2 + j * 16 + b_k8) * 2;
                uint32_t r0, r1, r2, r3;
                ldsm_x4(r0, r1, r2, r3, addr);
                b[nt2 * 2][0] = r0; b[nt2 * 2][1] = r1;
                b[nt2 * 2 + 1][0] = r2; b[nt2 * 2 + 1][1] = r3;
            }
#pragma unroll
            for (int mt = 0; mt < 4; mt++)
#pragma unroll
                for (int nt = 0; nt < 8; nt++)
                    mma_fp16(acc[mt][nt][0], acc[mt][nt][1], acc[mt][nt][2], acc[mt][nt][3],
                             a[mt][0], a[mt][1], a[mt][2], a[mt][3], b[nt][0], b[nt][1]);
        }
    }

    const int er = lane >> 2;
    const int ec = (lane & 3) * 2;
    float* part = (EPI == 4) ? Part + (size_t)blockIdx.z * KT * KE : nullptr;

#pragma unroll
    for (int nt = 0; nt < 8; nt++) {
        const int c = col0 + warp_n * 64 + nt * 8 + ec;
        const float b0 = (EPI == 4) ? 0.f : __ldg(bias + c);
        const float b1 = (EPI == 4) ? 0.f : __ldg(bias + c + 1);
#pragma unroll
        for (int mt = 0; mt < 4; mt++) {
            const int rl = row0 + warp_m * 64 + mt * 16 + er;
#pragma unroll
            for (int half = 0; half < 2; half++) {
                const size_t r = (size_t)(rl + half * 8);
                float v0 = acc[mt][nt][half * 2 + 0] + b0;
                float v1 = acc[mt][nt][half * 2 + 1] + b1;
                if (EPI == 2) {
                    const float2 rv = *(const float2*)(res + r * N + c);
                    v0 += rv.x; v1 += rv.y;
                    *(float2*)(Cf + r * N + c) = make_float2(v0, v1);
                } else if (EPI == 3) {
                    v0 = gelu_exact(v0); v1 = gelu_exact(v1);
                    *(uint32_t*)(C16 + r * N + c) = (uint32_t)f2h(v0) | ((uint32_t)f2h(v1) << 16);
                } else {
                    *(float2*)(part + r * N + c) = make_float2(v0, v1);
                }
            }
        }
    }
}

// ---------------- split-K reduce: out = p0 + p1 + bias + x2 ------------------
__global__ void reduce_kernel(const float* __restrict__ x2, const float* __restrict__ bias,
                              float* __restrict__ out) {
    const size_t i = (size_t)blockIdx.x * 256 + threadIdx.x;   // float4 index
    const int c4 = (int)(i & (KE / 4 - 1));
    const float4 bv = ((const float4*)bias)[c4];
    float4 s = ((const float4*)g_part)[i];
    const float4 p1 = ((const float4*)(g_part + (size_t)KT * KE))[i];
    const float4 xv = ((const float4*)x2)[i];
    s.x = s.x + p1.x + xv.x + bv.x;
    s.y = s.y + p1.y + xv.y + bv.y;
    s.z = s.z + p1.z + xv.z + bv.z;
    s.w = s.w + p1.w + xv.w + bv.w;
    ((float4*)out)[i] = s;
}

// ---------------- launch ----------------
extern "C" void kernel_launch(void* const* d_in, const int* in_sizes, int n_in,
                              void* d_out, int out_size) {
    (void)in_sizes; (void)n_in; (void)out_size;
    const float* x      = (const float*)d_in[0];
    const float* memory = (const float*)d_in[1];
    const float* w_k    = (const float*)d_in[2];
    const float* b_k    = (const float*)d_in[3];
    const float* w_q    = (const float*)d_in[4];
    const float* b_q    = (const float*)d_in[5];
    const float* w_v    = (const float*)d_in[6];
    const float* b_v    = (const float*)d_in[7];
    const float* w_out  = (const float*)d_in[8];
    const float* b_out  = (const float*)d_in[9];
    const float* w_gw   = (const float*)d_in[10];
    const float* b_gw   = (const float*)d_in[11];
    const float* w_gf   = (const float*)d_in[12];
    const float* b_gf   = (const float*)d_in[13];
    const float* ln1_g  = (const float*)d_in[14];
    const float* ln1_b  = (const float*)d_in[15];
    const float* ln2_g  = (const float*)d_in[16];
    const float* ln2_b  = (const float*)d_in[17];
    const float* w_f1   = (const float*)d_in[18];
    const float* b_f1   = (const float*)d_in[19];
    const float* w_f2   = (const float*)d_in[20];
    const float* b_f2   = (const float*)d_in[21];

    float* out_x   = (float*)d_out;
    float* out_mem = out_x + (size_t)KT * KE;

    float *p_k, *p_q, *p_v, *p_x2, *p_part;
    uint16_t *p_xnh, *p_xnl, *p_ro, *p_f1;
    uint16_t *p_wkqv, *p_wo, *p_wf1, *p_wf2;
    cudaGetSymbolAddress((void**)&p_k,    g_k);
    cudaGetSymbolAddress((void**)&p_q,    g_q);
    cudaGetSymbolAddress((void**)&p_v,    g_v);
    cudaGetSymbolAddress((void**)&p_x2,   g_x2);
    cudaGetSymbolAddress((void**)&p_part, g_part);
    cudaGetSymbolAddress((void**)&p_xnh,  g_xn_hi);
    cudaGetSymbolAddress((void**)&p_xnl,  g_xn_lo);
    cudaGetSymbolAddress((void**)&p_ro,   g_ro);
    cudaGetSymbolAddress((void**)&p_f1,   g_f1);
    cudaGetSymbolAddress((void**)&p_wkqv, g_wkqv_h);
    cudaGetSymbolAddress((void**)&p_wo,   g_wo_h);
    cudaGetSymbolAddress((void**)&p_wf1,  g_wf1_h);
    cudaGetSymbolAddress((void**)&p_wf2,  g_wf2_h);

    cudaFuncSetAttribute(gemm_kqv,  cudaFuncAttributeMaxDynamicSharedMemorySize, F2SMEM);
    cudaFuncSetAttribute(gemm1t<2>, cudaFuncAttributeMaxDynamicSharedMemorySize, G1SMEM);
    cudaFuncSetAttribute(gemm1t<3>, cudaFuncAttributeMaxDynamicSharedMemorySize, G1SMEM);
    cudaFuncSetAttribute(gemm1t<4>, cudaFuncAttributeMaxDynamicSharedMemorySize, G1SMEM);

    // launch order: ncu captures OUR index 3 -> kqv GEMM (clock-control probe)
    // 0) fused convert of w_k|w_q|w_v -> fp16
    convh3_kernel<<<768, 256>>>(w_k, w_q, w_v, p_wkqv, KM*KE/4);
    // 1) LN1 -> xn fp16 hi/lo
    ln_kernel<<<KT, 256>>>(x, ln1_g, ln1_b, p_xnh, p_xnl);
    // 2) convert w_out -> fp16
    convh_kernel<<<(KE*KM/4 + 1023)/1024, 256>>>(w_out, p_wo, KE*KM/4);
    // 3) fused kqv GEMM (fp16x2 fused-term, BK=32)  [profiled]
    gemm_kqv<<<dim3(6, KT/128), 128, F2SMEM>>>(
        p_xnh, p_xnl, p_wkqv, p_k, p_q, p_v, b_k, b_q, b_v, KE);
    // 4-5) convert FFN weights -> fp16
    convh_kernel<<<(KF*KE/4 + 1023)/1024, 256>>>(w_f1, p_wf1, KF*KE/4);
    convh_kernel<<<(KE*KF/4 + 1023)/1024, 256>>>(w_f2, p_wf2, KE*KF/4);
    // 6) l2norm + gates
    postproc_kernel<<<KT, 256>>>(w_gw, b_gw, w_gf, b_gf);
    // 7) chunk decay products
    chunkprod_kernel<<<KB * KC, KL>>>();
    // 8) scan pass A
    scanA_kernel<<<KC * KB * 32, 256>>>();
    // 9) scan pass B (+ final memory output)
    scanB_kernel<<<KB * KM, 256>>>(memory, out_mem);
    // 10) scan pass C (readouts -> fp16 single)
    scanC_kernel<<<KC * KB * 32, 256>>>();
    // 11) out projection + residual(x) -> x2 (fp16x1, BK=64)
    gemm1t<2><<<dim3(KE/128, KT/128), 128, G1SMEM>>>(
        p_ro, p_wo, b_out, x, p_x2, nullptr, nullptr, KM, KM, KE);
    // 12) LN2 -> xn fp16 hi/lo (FFN1 reads hi only)
    ln_kernel<<<KT, 256>>>(p_x2, ln2_g, ln2_b, p_xnh, p_xnl);
    // 13) FFN1 + GELU -> f1 fp16 single (fp16x1, BK=64)
    gemm1t<3><<<dim3(KF/128, KT/128), 128, G1SMEM>>>(
        p_xnh, p_wf1, b_f1, nullptr, nullptr, p_f1, nullptr, KE, KE, KF);
    // 14) FFN2 split-K=2 -> partials (fp16x1, BK=64)
    gemm1t<4><<<dim3(KE/128, KT/128, KSK), 128, G1SMEM>>>(
        p_f1, p_wf2, nullptr, nullptr, nullptr, nullptr, p_part, KF, KF/KSK, KE);
    // 15) reduce partials + bias + residual(x2) -> out
    reduce_kernel<<<KT * KE / 4 / 256, 256>>>(p_x2, b_f2, out_x);
}